// round 8
// baseline (speedup 1.0000x reference)
#include <cuda_runtime.h>
#include <cuda_bf16.h>
#include <math.h>
#include <stdint.h>

#define NN 100000
#define EE 800000
#define HID 128
#define NH 4
#define DH 32
#define NBLK ((NN + 1023) / 1024)   // 98
#define NPAD 100096
#define EPAD 68
#define TWW (128 * EPAD)            // W image words in smem (8704)
#define TAW (64 * EPAD)             // A image words in smem (4352)
#define AHI_OFF TWW
#define ALO_OFF (TWW + TAW)
#define ESM_WORDS (TWW + 2 * TAW)   // 17408 words
#define ESM_BYTES (ESM_WORDS * 4)   // 69632 B -> 3 blocks/SM

// ---------------- scratch (static device globals; no allocation) ----------------
__device__ unsigned int g_Ahi[(size_t)EE * 64];   // edge feats bf16-hi pairs [e][kw]
__device__ unsigned int g_Alo[(size_t)EE * 64];
__device__ unsigned int g_hhi[(size_t)NPAD * 64]; // hidden bf16 pair images (zero-padded)
__device__ unsigned int g_hlo[(size_t)NPAD * 64];
__device__ float g_xl[NN * HID];
__device__ float g_xr[NN * HID];
__device__ float g_h [NN * HID];
__device__ float g_score[EE * NH];
__device__ unsigned int g_WhiE[8192], g_WloE[8192];
__device__ unsigned int g_WhiL[8192], g_WloL[8192];
__device__ unsigned int g_WhiR[8192], g_WloR[8192];
__device__ int g_deg[NN], g_cursor[NN], g_rowptr[NN + 1], g_eids[EE];
__device__ int g_bsum[NBLK], g_boff[NBLK];

// ---------------- helpers ----------------
__device__ __forceinline__ float fast_silu(float z) {
    return __fdividef(z, 1.0f + __expf(-z));
}
__device__ __forceinline__ unsigned int packbf2(float x, float y) {
    __nv_bfloat162 t = __floats2bfloat162_rn(x, y);
    return *(unsigned int*)&t;
}
__device__ __forceinline__ void bf_split(float x, float& hi, float& lo) {
    __nv_bfloat16 h = __float2bfloat16_rn(x);
    hi = __bfloat162float(h);
    lo = x - hi;
}
__device__ __forceinline__ void mma_bf16(float c[4],
                                         unsigned int a0, unsigned int a1,
                                         unsigned int a2, unsigned int a3,
                                         unsigned int b0, unsigned int b1) {
    asm volatile("mma.sync.aligned.m16n8k16.row.col.f32.bf16.bf16.f32 "
                 "{%0,%1,%2,%3}, {%4,%5,%6,%7}, {%8,%9}, {%0,%1,%2,%3};"
                 : "+f"(c[0]), "+f"(c[1]), "+f"(c[2]), "+f"(c[3])
                 : "r"(a0), "r"(a1), "r"(a2), "r"(a3), "r"(b0), "r"(b1));
}
__device__ __forceinline__ uint32_t smem_u32(const void* p) {
    uint32_t a;
    asm("{ .reg .u64 t; cvta.to.shared.u64 t, %1; cvt.u32.u64 %0, t; }" : "=r"(a) : "l"(p));
    return a;
}
__device__ __forceinline__ void cp16(uint32_t d, const void* s) {
    size_t gs = __cvta_generic_to_global((void*)s);
    asm volatile("cp.async.cg.shared.global [%0], [%1], 16;"
                 :: "r"(d), "l"((unsigned long long)gs) : "memory");
}
__device__ __forceinline__ void cp_commit() {
    asm volatile("cp.async.commit_group;" ::: "memory");
}
template <int N>
__device__ __forceinline__ void cp_wait() {
    asm volatile("cp.async.wait_group %0;" :: "n"(N) : "memory");
}

// ---------------- edge feature projection: bf16 hi/lo pair images ----------------
__global__ void eproj_kernel(const float* __restrict__ attr,
                             const float* __restrict__ W,
                             const float* __restrict__ b) {
    int idx = blockIdx.x * blockDim.x + threadIdx.x;   // E*32 threads
    int e = idx >> 5, c4 = (idx & 31) << 2;
    float a0 = __ldg(&attr[e * 3 + 0]);
    float a1 = __ldg(&attr[e * 3 + 1]);
    float a2 = __ldg(&attr[e * 3 + 2]);
    float v[4];
#pragma unroll
    for (int u = 0; u < 4; u++) {
        int j = c4 + u;
        float z = __ldg(&b[j]);
        z = fmaf(a0, __ldg(&W[j]),           z);
        z = fmaf(a1, __ldg(&W[HID + j]),     z);
        z = fmaf(a2, __ldg(&W[2 * HID + j]), z);
        v[u] = fast_silu(z);
    }
    float h0, l0, h1, l1, h2, l2, h3, l3;
    bf_split(v[0], h0, l0); bf_split(v[1], h1, l1);
    bf_split(v[2], h2, l2); bf_split(v[3], h3, l3);
    size_t base = (size_t)e * 64 + (c4 >> 1);
    *(uint2*)&g_Ahi[base] = make_uint2(packbf2(h0, h1), packbf2(h2, h3));
    *(uint2*)&g_Alo[base] = make_uint2(packbf2(l0, l1), packbf2(l2, l3));
}

// ---------------- CSR build (by dst) ----------------
__global__ void zero_kernel() {
    int i = blockIdx.x * blockDim.x + threadIdx.x;
    if (i < NN) { g_deg[i] = 0; g_cursor[i] = 0; }
}
__global__ void hist_kernel(const int* __restrict__ ei) {
    int e = blockIdx.x * blockDim.x + threadIdx.x;
    if (e < EE) atomicAdd(&g_deg[ei[EE + e]], 1);
}
__global__ void deg_block_sum() {
    __shared__ int sh[1024];
    int i = blockIdx.x * 1024 + threadIdx.x;
    sh[threadIdx.x] = (i < NN) ? g_deg[i] : 0;
    __syncthreads();
    for (int off = 512; off; off >>= 1) {
        if (threadIdx.x < off) sh[threadIdx.x] += sh[threadIdx.x + off];
        __syncthreads();
    }
    if (threadIdx.x == 0) g_bsum[blockIdx.x] = sh[0];
}
__global__ void bsum_scan() {
    __shared__ int sh[128];
    int t = threadIdx.x;
    int v = (t < NBLK) ? g_bsum[t] : 0;
    sh[t] = v;
    __syncthreads();
    for (int off = 1; off < 128; off <<= 1) {
        int u = (t >= off) ? sh[t - off] : 0;
        __syncthreads();
        sh[t] += u;
        __syncthreads();
    }
    if (t < NBLK) g_boff[t] = sh[t] - v;
}
__global__ void rowptr_kernel() {
    __shared__ int sh[1024];
    int i = blockIdx.x * 1024 + threadIdx.x;
    int v = (i < NN) ? g_deg[i] : 0;
    sh[threadIdx.x] = v;
    __syncthreads();
    for (int off = 1; off < 1024; off <<= 1) {
        int u = (threadIdx.x >= off) ? sh[threadIdx.x - off] : 0;
        __syncthreads();
        sh[threadIdx.x] += u;
        __syncthreads();
    }
    if (i < NN) g_rowptr[i + 1] = sh[threadIdx.x] + g_boff[blockIdx.x];
    if (i == 0) g_rowptr[0] = 0;
}
__global__ void scatter_kernel(const int* __restrict__ ei) {
    int e = blockIdx.x * blockDim.x + threadIdx.x;
    if (e < EE) {
        int d = ei[EE + e];
        int pos = atomicAdd(&g_cursor[d], 1);
        g_eids[g_rowptr[d] + pos] = e;
    }
}

// ---------------- W image prep ----------------
// which: 0 -> We, 1 -> Wl, 2 -> Wr
__global__ void wprep_kernel(const float* __restrict__ W, int which) {
    int idx = blockIdx.x * 256 + threadIdx.x;   // 8192
    int n = idx >> 6, kw = idx & 63;
    float w0 = __ldg(&W[(2 * kw) * HID + n]);
    float w1 = __ldg(&W[(2 * kw + 1) * HID + n]);
    float h0, l0, h1, l1;
    bf_split(w0, h0, l0);
    bf_split(w1, h1, l1);
    unsigned int* hi = (which == 0) ? g_WhiE : (which == 1) ? g_WhiL : g_WhiR;
    unsigned int* lo = (which == 0) ? g_WloE : (which == 1) ? g_WloL : g_WloR;
    hi[idx] = packbf2(h0, h1);
    lo[idx] = packbf2(l0, l1);
}

// ======= shared staging + mma core for a 64-row tile =======
__device__ __forceinline__ void stage_tile(unsigned int* esm, uint32_t sb,
                                           const unsigned int* gAhi,
                                           const unsigned int* gAlo,
                                           const unsigned int* gWhi,
                                           int m0, int tid) {
    // A hi/lo via cp.async: 64 rows x 64 words, 16B chunks
#pragma unroll
    for (int i = 0; i < 4; i++) {
        int idx = i * 256 + tid;                  // 0..1023
        int row = idx >> 4, c = (idx & 15) << 2;
        uint32_t doff = (uint32_t)(row * EPAD + c) * 4;
        cp16(sb + AHI_OFF * 4 + doff, &gAhi[(size_t)(m0 + row) * 64 + c]);
        cp16(sb + ALO_OFF * 4 + doff, &gAlo[(size_t)(m0 + row) * 64 + c]);
    }
    cp_commit();
    // Whi via regular loads (L2-resident, shared by all blocks)
#pragma unroll
    for (int i = 0; i < 8; i++) {
        int idx = i * 256 + tid;                  // 0..2047 uint4
        int n = idx >> 4, c = (idx & 15) << 2;
        uint4 vh = ((const uint4*)gWhi)[idx];
        *(uint4*)&esm[n * EPAD + c] = vh;
    }
    cp_wait<0>();
    __syncthreads();
}

// 3-pass bf16x3 mma; pass 1's B (Wlo) comes straight from global (L1-hot).
__device__ __forceinline__ void tile_mma64(float acc[2][4][4],
                                           const unsigned int* esm,
                                           const unsigned int* gWlo,
                                           int mb, int nb, int g, int q) {
#pragma unroll
    for (int t = 0; t < 2; t++)
#pragma unroll
        for (int j = 0; j < 4; j++)
#pragma unroll
            for (int c = 0; c < 4; c++) acc[t][j][c] = 0.f;

#pragma unroll
    for (int pass = 0; pass < 3; pass++) {
        const unsigned int* As = (pass == 2) ? esm + ALO_OFF : esm + AHI_OFF;
#pragma unroll
        for (int ks = 0; ks < 8; ks++) {
            int kw0 = ks * 8 + q;
            unsigned int a[2][4];
#pragma unroll
            for (int t = 0; t < 2; t++) {
                int r = mb + 16 * t + g;
                a[t][0] = As[r * EPAD + kw0];
                a[t][1] = As[(r + 8) * EPAD + kw0];
                a[t][2] = As[r * EPAD + kw0 + 4];
                a[t][3] = As[(r + 8) * EPAD + kw0 + 4];
            }
            unsigned int b[4][2];
#pragma unroll
            for (int j = 0; j < 4; j++) {
                int n = nb + 8 * j + g;
                if (pass == 1) {
                    b[j][0] = __ldg(&gWlo[n * 64 + kw0]);
                    b[j][1] = __ldg(&gWlo[n * 64 + kw0 + 4]);
                } else {
                    b[j][0] = esm[n * EPAD + kw0];
                    b[j][1] = esm[n * EPAD + kw0 + 4];
                }
            }
#pragma unroll
            for (int t = 0; t < 2; t++)
#pragma unroll
                for (int j = 0; j < 4; j++)
                    mma_bf16(acc[t][j], a[t][0], a[t][1], a[t][2], a[t][3],
                             b[j][0], b[j][1]);
        }
    }
}

// ================= edge GEMM + fused attention score (64-row tiles) =============
__global__ __launch_bounds__(256, 3) void gemm_edge_score_mma(
        const float* __restrict__ att, const int* __restrict__ ei) {
    extern __shared__ __align__(16) unsigned int esm[];
    uint32_t sb = smem_u32(esm);
    int tid = threadIdx.x;
    int m0 = blockIdx.x * 64;

    stage_tile(esm, sb, g_Ahi, g_Alo, g_WhiE, m0, tid);

    int wid = tid >> 5, lane = tid & 31, g = lane >> 2, q = lane & 3;
    int mb = (wid & 1) * 32;        // 2 row groups
    int nb = (wid >> 1) * 32;       // 4 col groups (one head each)

    float acc[2][4][4];
    tile_mma64(acc, esm, g_WloE, mb, nb, g, q);

    float2 attv[4];
#pragma unroll
    for (int j = 0; j < 4; j++)
        attv[j] = *(const float2*)&att[nb + 8 * j + 2 * q];

#pragma unroll
    for (int t = 0; t < 2; t++) {
#pragma unroll
        for (int rr = 0; rr < 2; rr++) {
            int row = mb + 16 * t + 8 * rr + g;
            int edge = m0 + row;
            int src = __ldg(&ei[edge]);
            int dst = __ldg(&ei[EE + edge]);
            const float* xlp = &g_xl[(size_t)src * HID];
            const float* xrp = &g_xr[(size_t)dst * HID];
            float p = 0.f;
#pragma unroll
            for (int j = 0; j < 4; j++) {
                int cc = nb + 8 * j + 2 * q;
                float2 xl = *(const float2*)&xlp[cc];
                float2 xr = *(const float2*)&xrp[cc];
                float e0 = acc[t][j][rr * 2 + 0] + xl.x + xr.x;
                float e1 = acc[t][j][rr * 2 + 1] + xl.y + xr.y;
                e0 = (e0 > 0.f) ? e0 : 0.2f * e0;
                e1 = (e1 > 0.f) ? e1 : 0.2f * e1;
                p += fmaf(e0, attv[j].x, e1 * attv[j].y);
            }
            p += __shfl_xor_sync(0xffffffffu, p, 1);
            p += __shfl_xor_sync(0xffffffffu, p, 2);
            if (q == 0)
                g_score[(size_t)edge * 4 + (nb >> 5)] = p;
        }
    }
}

// ================= node GEMM (same machinery; xl / xr via blockIdx.y) ===========
__global__ __launch_bounds__(256, 3) void gemm_node_mma(
        const float* __restrict__ bl, const float* __restrict__ br) {
    extern __shared__ __align__(16) unsigned int esm[];
    uint32_t sb = smem_u32(esm);
    int tid = threadIdx.x;
    int m0 = blockIdx.x * 64;

    const unsigned int* gWhi = blockIdx.y ? g_WhiR : g_WhiL;
    const unsigned int* gWlo = blockIdx.y ? g_WloR : g_WloL;
    float* C = blockIdx.y ? g_xr : g_xl;
    const float* bias = blockIdx.y ? br : bl;

    stage_tile(esm, sb, g_hhi, g_hlo, gWhi, m0, tid);

    int wid = tid >> 5, lane = tid & 31, g = lane >> 2, q = lane & 3;
    int mb = (wid & 1) * 32;
    int nb = (wid >> 1) * 32;

    float acc[2][4][4];
    tile_mma64(acc, esm, gWlo, mb, nb, g, q);

    float2 biasv[4];
#pragma unroll
    for (int j = 0; j < 4; j++)
        biasv[j] = *(const float2*)&bias[nb + 8 * j + 2 * q];

#pragma unroll
    for (int t = 0; t < 2; t++) {
#pragma unroll
        for (int rr = 0; rr < 2; rr++) {
            int m = m0 + mb + 16 * t + 8 * rr + g;
            if (m < NN) {
#pragma unroll
                for (int j = 0; j < 4; j++) {
                    int cc = nb + 8 * j + 2 * q;
                    *(float2*)&C[(size_t)m * HID + cc] =
                        make_float2(acc[t][j][rr * 2 + 0] + biasv[j].x,
                                    acc[t][j][rr * 2 + 1] + biasv[j].y);
                }
            }
        }
    }
}

// ---------------- layer-0 node projection (K=12) ----------------
__global__ void node_proj12(const float* __restrict__ x,
                            const float* __restrict__ Wl, const float* __restrict__ bl,
                            const float* __restrict__ Wr, const float* __restrict__ br) {
    int idx = blockIdx.x * blockDim.x + threadIdx.x;
    int n = idx >> 7, j = idx & 127;
    float a = __ldg(&bl[j]);
    float b = __ldg(&br[j]);
#pragma unroll
    for (int k = 0; k < 12; k++) {
        float xv = __ldg(&x[n * 12 + k]);
        a = fmaf(xv, __ldg(&Wl[k * HID + j]), a);
        b = fmaf(xv, __ldg(&Wr[k * HID + j]), b);
    }
    g_xl[idx] = a;
    g_xr[idx] = b;
}

// ---------------- fused per-node: softmax + aggregate + bias + LN + SiLU (+res) ---
template <bool RES, bool LAST>
__global__ void node_fused_kernel(const int* __restrict__ ei,
                                  const float* __restrict__ gat_bias,
                                  const float* __restrict__ lng,
                                  const float* __restrict__ lnb,
                                  float* __restrict__ dout) {
    int n = blockIdx.x * 4 + (threadIdx.x >> 5);
    int lane = threadIdx.x & 31;
    if (n >= NN) return;
    int s0 = g_rowptr[n];
    int s1 = g_rowptr[n + 1];

    float mx = -3.4e38f;
    for (int p = s0 * 4 + lane; p < s1 * 4; p += 32) {
        int e = g_eids[p >> 2];
        mx = fmaxf(mx, g_score[(size_t)e * 4 + (p & 3)]);
    }
    mx = fmaxf(mx, __shfl_xor_sync(0xffffffffu, mx, 4));
    mx = fmaxf(mx, __shfl_xor_sync(0xffffffffu, mx, 8));
    mx = fmaxf(mx, __shfl_xor_sync(0xffffffffu, mx, 16));

    float den = 0.f;
    for (int p = s0 * 4 + lane; p < s1 * 4; p += 32) {
        int e = g_eids[p >> 2];
        den += __expf(g_score[(size_t)e * 4 + (p & 3)] - mx);
    }
    den += __shfl_xor_sync(0xffffffffu, den, 4);
    den += __shfl_xor_sync(0xffffffffu, den, 8);
    den += __shfl_xor_sync(0xffffffffu, den, 16);
    float inv = __fdividef(1.f, den + 1e-16f);

    float acc0 = 0.f, acc1 = 0.f, acc2 = 0.f, acc3 = 0.f;
    for (int i = s0; i < s1; i++) {
        int e = g_eids[i];
        int src = ei[e];
        float a = 0.f;
        if (lane < 4) a = __expf(g_score[(size_t)e * 4 + lane] - mx) * inv;
        float al0 = __shfl_sync(0xffffffffu, a, 0);
        float al1 = __shfl_sync(0xffffffffu, a, 1);
        float al2 = __shfl_sync(0xffffffffu, a, 2);
        float al3 = __shfl_sync(0xffffffffu, a, 3);
        const float* xl = &g_xl[(size_t)src * HID];
        acc0 = fmaf(xl[0 * DH + lane], al0, acc0);
        acc1 = fmaf(xl[1 * DH + lane], al1, acc1);
        acc2 = fmaf(xl[2 * DH + lane], al2, acc2);
        acc3 = fmaf(xl[3 * DH + lane], al3, acc3);
    }

    float v0 = acc0 + __ldg(&gat_bias[0 * DH + lane]);
    float v1 = acc1 + __ldg(&gat_bias[1 * DH + lane]);
    float v2 = acc2 + __ldg(&gat_bias[2 * DH + lane]);
    float v3 = acc3 + __ldg(&gat_bias[3 * DH + lane]);

    float sm = v0 + v1 + v2 + v3;
#pragma unroll
    for (int off = 16; off; off >>= 1) sm += __shfl_xor_sync(0xffffffffu, sm, off);
    float mean = sm * (1.f / 128.f);
    float d0 = v0 - mean, d1 = v1 - mean, d2 = v2 - mean, d3 = v3 - mean;
    float sq = d0 * d0 + d1 * d1 + d2 * d2 + d3 * d3;
#pragma unroll
    for (int off = 16; off; off >>= 1) sq += __shfl_xor_sync(0xffffffffu, sq, off);
    float rstd = rsqrtf(sq * (1.f / 128.f) + 1e-5f);

#pragma unroll
    for (int h = 0; h < 4; h++) {
        int j = h * DH + lane;
        float d = (h == 0 ? d0 : h == 1 ? d1 : h == 2 ? d2 : d3);
        float t = fmaf(d * rstd, __ldg(&lng[j]), __ldg(&lnb[j]));
        float sil = fast_silu(t);
        float o = RES ? (g_h[n * HID + j] + sil) : sil;
        if (LAST) {
            dout[n * HID + j] = o;
        } else {
            g_h[n * HID + j] = o;
            // bf16 split pair images for the next layer's node GEMM
            float on = __shfl_down_sync(0xffffffffu, o, 1);
            if (!(lane & 1)) {
                float h0, l0, h1, l1;
                bf_split(o, h0, l0);
                bf_split(on, h1, l1);
                g_hhi[(size_t)n * 64 + (j >> 1)] = packbf2(h0, h1);
                g_hlo[(size_t)n * 64 + (j >> 1)] = packbf2(l0, l1);
            }
        }
    }
}

// ---------------- launch ----------------
extern "C" void kernel_launch(void* const* d_in, const int* in_sizes, int n_in,
                              void* d_out, int out_size) {
    const float* x     = (const float*)d_in[0];
    const int*   ei    = (const int*)  d_in[1];
    const float* eattr = (const float*)d_in[2];
    const float* epw   = (const float*)d_in[3];
    const float* epb   = (const float*)d_in[4];
    const float* l0Wl  = (const float*)d_in[5];
    const float* l0bl  = (const float*)d_in[6];
    const float* l0Wr  = (const float*)d_in[7];
    const float* l0br  = (const float*)d_in[8];
    const float* l0We  = (const float*)d_in[9];
    const float* l0att = (const float*)d_in[10];
    const float* l0bias= (const float*)d_in[11];
    const float* Wl    = (const float*)d_in[12];
    const float* bl    = (const float*)d_in[13];
    const float* Wr    = (const float*)d_in[14];
    const float* br    = (const float*)d_in[15];
    const float* We    = (const float*)d_in[16];
    const float* att   = (const float*)d_in[17];
    const float* bias  = (const float*)d_in[18];
    const float* lng   = (const float*)d_in[19];
    const float* lnb   = (const float*)d_in[20];
    float* out = (float*)d_out;

    static bool attr_set = false;
    if (!attr_set) {
        cudaFuncSetAttribute(gemm_edge_score_mma,
                             cudaFuncAttributeMaxDynamicSharedMemorySize, ESM_BYTES);
        cudaFuncSetAttribute(gemm_node_mma,
                             cudaFuncAttributeMaxDynamicSharedMemorySize, ESM_BYTES);
        attr_set = true;
    }

    // layer-0 prerequisites; edge GEMM kept at 4th launch for ncu capture
    eproj_kernel<<<(EE * 32) / 256, 256>>>(eattr, epw, epb);
    node_proj12<<<(NN * HID) / 256, 256>>>(x, l0Wl, l0bl, l0Wr, l0br);
    wprep_kernel<<<32, 256>>>(l0We, 0);
    gemm_edge_score_mma<<<EE / 64, 256, ESM_BYTES>>>(l0att, ei);

    // CSR build
    zero_kernel<<<(NN + 255) / 256, 256>>>();
    hist_kernel<<<(EE + 255) / 256, 256>>>(ei);
    deg_block_sum<<<NBLK, 1024>>>();
    bsum_scan<<<1, 128>>>();
    rowptr_kernel<<<NBLK, 1024>>>();
    scatter_kernel<<<(EE + 255) / 256, 256>>>(ei);

    node_fused_kernel<false, false><<<NN / 4, 128>>>(ei, l0bias, lng, lnb, nullptr);

    // layers 1..3 (residual)
    for (int i = 0; i < 3; i++) {
        wprep_kernel<<<32, 256>>>(Wl + i * HID * HID, 1);
        wprep_kernel<<<32, 256>>>(Wr + i * HID * HID, 2);
        wprep_kernel<<<32, 256>>>(We + i * HID * HID, 0);
        dim3 ng(NPAD / 64, 2);   // 1564 x 2
        gemm_node_mma<<<ng, 256, ESM_BYTES>>>(bl + i * HID, br + i * HID);
        gemm_edge_score_mma<<<EE / 64, 256, ESM_BYTES>>>(att + i * HID, ei);
        if (i < 2)
            node_fused_kernel<true, false><<<NN / 4, 128>>>(
                ei, bias + i * HID, lng + (i + 1) * HID, lnb + (i + 1) * HID, nullptr);
        else
            node_fused_kernel<true, true><<<NN / 4, 128>>>(
                ei, bias + i * HID, lng + (i + 1) * HID, lnb + (i + 1) * HID, out);
    }
}

// round 9
// speedup vs baseline: 1.8494x; 1.8494x over previous
#include <cuda_runtime.h>
#include <cuda_bf16.h>
#include <math.h>
#include <stdint.h>

#define NN 100000
#define EE 800000
#define HID 128
#define NH 4
#define DH 32
#define NBLK ((NN + 1023) / 1024)   // 98
#define EPAD 68
#define TW (128 * EPAD)             // words per 128-row image (8704)
#define TB (TW * 4)                 // bytes per image (34816)
// smem: Whi | Wlo | A0hi | A0lo | A1hi | A1lo  = 6 images = 208896 B
#define ESM_BYTES (6 * TB)

// ---------------- scratch (static device globals; no allocation) ----------------
__device__ unsigned int g_Ahi[(size_t)EE * 64];   // edge feats bf16-hi pairs [e][kw]
__device__ unsigned int g_Alo[(size_t)EE * 64];
__device__ float g_xl[NN * HID];
__device__ float g_xr[NN * HID];
__device__ float g_h [NN * HID];
__device__ float g_score[EE * NH];
__device__ unsigned int g_WhiE[8192], g_WloE[8192];   // We^T bf16-pair images
__device__ int g_deg[NN], g_cursor[NN], g_rowptr[NN + 1];
__device__ int g_eids[EE], g_srcs[EE];
__device__ int g_bsum[NBLK], g_boff[NBLK];

// ---------------- helpers ----------------
__device__ __forceinline__ float fast_silu(float z) {
    return __fdividef(z, 1.0f + __expf(-z));
}
__device__ __forceinline__ unsigned int packbf2(float x, float y) {
    __nv_bfloat162 t = __floats2bfloat162_rn(x, y);
    return *(unsigned int*)&t;
}
__device__ __forceinline__ void bf_split(float x, float& hi, float& lo) {
    __nv_bfloat16 h = __float2bfloat16_rn(x);
    hi = __bfloat162float(h);
    lo = x - hi;
}
__device__ __forceinline__ void mma_bf16(float c[4],
                                         unsigned int a0, unsigned int a1,
                                         unsigned int a2, unsigned int a3,
                                         unsigned int b0, unsigned int b1) {
    asm volatile("mma.sync.aligned.m16n8k16.row.col.f32.bf16.bf16.f32 "
                 "{%0,%1,%2,%3}, {%4,%5,%6,%7}, {%8,%9}, {%0,%1,%2,%3};"
                 : "+f"(c[0]), "+f"(c[1]), "+f"(c[2]), "+f"(c[3])
                 : "r"(a0), "r"(a1), "r"(a2), "r"(a3), "r"(b0), "r"(b1));
}
// packed fp32x2 (FFMA2) for the node GEMM
__device__ __forceinline__ unsigned long long pack2(float x, float y) {
    unsigned long long r;
    asm("mov.b64 %0, {%1, %2};" : "=l"(r) : "f"(x), "f"(y));
    return r;
}
__device__ __forceinline__ unsigned long long bcast2(float x) {
    unsigned long long r;
    asm("mov.b64 %0, {%1, %1};" : "=l"(r) : "f"(x));
    return r;
}
__device__ __forceinline__ void ffma2(unsigned long long& d,
                                      unsigned long long a, unsigned long long b) {
    asm("fma.rn.f32x2 %0, %1, %2, %0;" : "+l"(d) : "l"(a), "l"(b));
}
__device__ __forceinline__ uint32_t smem_u32(const void* p) {
    uint32_t a;
    asm("{ .reg .u64 t; cvta.to.shared.u64 t, %1; cvt.u32.u64 %0, t; }" : "=r"(a) : "l"(p));
    return a;
}
__device__ __forceinline__ void cp16(uint32_t d, const void* s) {
    size_t gs = __cvta_generic_to_global((void*)s);
    asm volatile("cp.async.cg.shared.global [%0], [%1], 16;"
                 :: "r"(d), "l"((unsigned long long)gs) : "memory");
}
__device__ __forceinline__ void cp_commit() {
    asm volatile("cp.async.commit_group;" ::: "memory");
}
template <int N>
__device__ __forceinline__ void cp_wait() {
    asm volatile("cp.async.wait_group %0;" :: "n"(N) : "memory");
}

// ---------------- edge feature projection: bf16 hi/lo pair images ----------------
__global__ void eproj_kernel(const float* __restrict__ attr,
                             const float* __restrict__ W,
                             const float* __restrict__ b) {
    int idx = blockIdx.x * blockDim.x + threadIdx.x;   // E*32 threads
    int e = idx >> 5, c4 = (idx & 31) << 2;
    float a0 = __ldg(&attr[e * 3 + 0]);
    float a1 = __ldg(&attr[e * 3 + 1]);
    float a2 = __ldg(&attr[e * 3 + 2]);
    float v[4];
#pragma unroll
    for (int u = 0; u < 4; u++) {
        int j = c4 + u;
        float z = __ldg(&b[j]);
        z = fmaf(a0, __ldg(&W[j]),           z);
        z = fmaf(a1, __ldg(&W[HID + j]),     z);
        z = fmaf(a2, __ldg(&W[2 * HID + j]), z);
        v[u] = fast_silu(z);
    }
    float h0, l0, h1, l1, h2, l2, h3, l3;
    bf_split(v[0], h0, l0); bf_split(v[1], h1, l1);
    bf_split(v[2], h2, l2); bf_split(v[3], h3, l3);
    size_t base = (size_t)e * 64 + (c4 >> 1);
    *(uint2*)&g_Ahi[base] = make_uint2(packbf2(h0, h1), packbf2(h2, h3));
    *(uint2*)&g_Alo[base] = make_uint2(packbf2(l0, l1), packbf2(l2, l3));
}

// ---------------- CSR build (by dst) ----------------
__global__ void zero_kernel() {
    int i = blockIdx.x * blockDim.x + threadIdx.x;
    if (i < NN) { g_deg[i] = 0; g_cursor[i] = 0; }
}
__global__ void hist_kernel(const int* __restrict__ ei) {
    int e = blockIdx.x * blockDim.x + threadIdx.x;
    if (e < EE) atomicAdd(&g_deg[ei[EE + e]], 1);
}
__global__ void deg_block_sum() {
    __shared__ int sh[1024];
    int i = blockIdx.x * 1024 + threadIdx.x;
    sh[threadIdx.x] = (i < NN) ? g_deg[i] : 0;
    __syncthreads();
    for (int off = 512; off; off >>= 1) {
        if (threadIdx.x < off) sh[threadIdx.x] += sh[threadIdx.x + off];
        __syncthreads();
    }
    if (threadIdx.x == 0) g_bsum[blockIdx.x] = sh[0];
}
__global__ void bsum_scan() {
    __shared__ int sh[128];
    int t = threadIdx.x;
    int v = (t < NBLK) ? g_bsum[t] : 0;
    sh[t] = v;
    __syncthreads();
    for (int off = 1; off < 128; off <<= 1) {
        int u = (t >= off) ? sh[t - off] : 0;
        __syncthreads();
        sh[t] += u;
        __syncthreads();
    }
    if (t < NBLK) g_boff[t] = sh[t] - v;
}
__global__ void rowptr_kernel() {
    __shared__ int sh[1024];
    int i = blockIdx.x * 1024 + threadIdx.x;
    int v = (i < NN) ? g_deg[i] : 0;
    sh[threadIdx.x] = v;
    __syncthreads();
    for (int off = 1; off < 1024; off <<= 1) {
        int u = (threadIdx.x >= off) ? sh[threadIdx.x - off] : 0;
        __syncthreads();
        sh[threadIdx.x] += u;
        __syncthreads();
    }
    if (i < NN) g_rowptr[i + 1] = sh[threadIdx.x] + g_boff[blockIdx.x];
    if (i == 0) g_rowptr[0] = 0;
}
__global__ void scatter_kernel(const int* __restrict__ ei) {
    int e = blockIdx.x * blockDim.x + threadIdx.x;
    if (e < EE) {
        int src = ei[e];
        int d = ei[EE + e];
        int pos = g_rowptr[d] + atomicAdd(&g_cursor[d], 1);
        g_eids[pos] = e;
        g_srcs[pos] = src;
    }
}

// ---------------- W image prep (edge We) ----------------
__global__ void wprep_kernel(const float* __restrict__ W) {
    int idx = blockIdx.x * 256 + threadIdx.x;   // 8192
    int n = idx >> 6, kw = idx & 63;
    float w0 = __ldg(&W[(2 * kw) * HID + n]);
    float w1 = __ldg(&W[(2 * kw + 1) * HID + n]);
    float h0, l0, h1, l1;
    bf_split(w0, h0, l0);
    bf_split(w1, h1, l1);
    g_WhiE[idx] = packbf2(h0, h1);
    g_WloE[idx] = packbf2(l0, l1);
}

// ======= async staging helpers (128-row images, 16B chunks) =======
__device__ __forceinline__ void cp_image(uint32_t dst, const unsigned int* gsrc,
                                         int m0, int tid) {
#pragma unroll
    for (int i = 0; i < 8; i++) {
        int idx = i * 256 + tid;              // 2048 chunks
        int row = idx >> 4, c = (idx & 15) << 2;
        cp16(dst + (uint32_t)(row * EPAD + c) * 4,
             &gsrc[(size_t)(m0 + row) * 64 + c]);
    }
}

// ---- bf16x3 mma for one 128x128 tile (r5-validated fragment layout) ----
__device__ __forceinline__ void tile_mma(float acc[2][8][4],
                                         const unsigned int* Wsm,  // Whi | Wlo
                                         const unsigned int* Abuf, // Ahi | Alo
                                         int mb, int nb, int g, int q) {
#pragma unroll
    for (int t = 0; t < 2; t++)
#pragma unroll
        for (int j = 0; j < 8; j++)
#pragma unroll
            for (int c = 0; c < 4; c++) acc[t][j][c] = 0.f;

#pragma unroll
    for (int pass = 0; pass < 3; pass++) {
        const unsigned int* As = (pass == 2) ? Abuf + TW : Abuf;
        const unsigned int* Bs = (pass == 1) ? Wsm + TW : Wsm;
#pragma unroll
        for (int ks = 0; ks < 8; ks++) {
            int kw0 = ks * 8 + q;
            unsigned int a[2][4];
#pragma unroll
            for (int t = 0; t < 2; t++) {
                int r = mb + 16 * t + g;
                a[t][0] = As[r * EPAD + kw0];
                a[t][1] = As[(r + 8) * EPAD + kw0];
                a[t][2] = As[r * EPAD + kw0 + 4];
                a[t][3] = As[(r + 8) * EPAD + kw0 + 4];
            }
            unsigned int b[8][2];
#pragma unroll
            for (int j = 0; j < 8; j++) {
                int n = nb + 8 * j + g;
                b[j][0] = Bs[n * EPAD + kw0];
                b[j][1] = Bs[n * EPAD + kw0 + 4];
            }
#pragma unroll
            for (int t = 0; t < 2; t++)
#pragma unroll
                for (int j = 0; j < 8; j++)
                    mma_bf16(acc[t][j], a[t][0], a[t][1], a[t][2], a[t][3],
                             b[j][0], b[j][1]);
        }
    }
}

// ================= edge GEMM + fused score: 2 tiles/block, double-buffered ======
__global__ __launch_bounds__(256, 1) void gemm_edge_score_mma(
        const float* __restrict__ att, const int* __restrict__ ei) {
    extern __shared__ __align__(16) unsigned int esm[];
    uint32_t sb = smem_u32(esm);
    int tid = threadIdx.x;
    int mbase = blockIdx.x * 256;

    // group 0: A tile 0 (hi+lo); group 1: W (hi+lo); group 2: A tile 1
    cp_image(sb + 2 * TB, g_Ahi, mbase, tid);
    cp_image(sb + 3 * TB, g_Alo, mbase, tid);
    cp_commit();
    cp_image(sb + 0 * TB, (const unsigned int*)g_WhiE, 0, tid);
    cp_image(sb + 1 * TB, (const unsigned int*)g_WloE, 0, tid);
    cp_commit();
    cp_image(sb + 4 * TB, g_Ahi, mbase + 128, tid);
    cp_image(sb + 5 * TB, g_Alo, mbase + 128, tid);
    cp_commit();

    int wid = tid >> 5, lane = tid & 31, g = lane >> 2, q = lane & 3;
    int mb = (wid & 3) * 32;        // 4 row groups
    int nb = (wid >> 2) * 64;       // 2 col groups (2 heads each)

    float2 attv[8];
#pragma unroll
    for (int j = 0; j < 8; j++)
        attv[j] = *(const float2*)&att[nb + 8 * j + 2 * q];

#pragma unroll
    for (int tt = 0; tt < 2; tt++) {
        if (tt == 0) cp_wait<1>();   // A0 + W done (A1 may still fly)
        else         cp_wait<0>();
        __syncthreads();

        int m0 = mbase + tt * 128;
        const unsigned int* Abuf = esm + (2 + 2 * tt) * TW;
        float acc[2][8][4];
        tile_mma(acc, esm, Abuf, mb, nb, g, q);

        // fused epilogue
#pragma unroll
        for (int t = 0; t < 2; t++) {
#pragma unroll
            for (int rr = 0; rr < 2; rr++) {
                int row = mb + 16 * t + 8 * rr + g;
                int edge = m0 + row;
                int src = __ldg(&ei[edge]);
                int dst = __ldg(&ei[EE + edge]);
                const float* xlp = &g_xl[(size_t)src * HID];
                const float* xrp = &g_xr[(size_t)dst * HID];
                float p0 = 0.f, p1 = 0.f;
#pragma unroll
                for (int j = 0; j < 8; j++) {
                    int cc = nb + 8 * j + 2 * q;
                    float2 xl = *(const float2*)&xlp[cc];
                    float2 xr = *(const float2*)&xrp[cc];
                    float e0 = acc[t][j][rr * 2 + 0] + xl.x + xr.x;
                    float e1 = acc[t][j][rr * 2 + 1] + xl.y + xr.y;
                    e0 = (e0 > 0.f) ? e0 : 0.2f * e0;
                    e1 = (e1 > 0.f) ? e1 : 0.2f * e1;
                    float ps = fmaf(e0, attv[j].x, e1 * attv[j].y);
                    if (j < 4) p0 += ps; else p1 += ps;
                }
                p0 += __shfl_xor_sync(0xffffffffu, p0, 1);
                p0 += __shfl_xor_sync(0xffffffffu, p0, 2);
                p1 += __shfl_xor_sync(0xffffffffu, p1, 1);
                p1 += __shfl_xor_sync(0xffffffffu, p1, 2);
                if (q == 0)
                    *(float2*)&g_score[(size_t)edge * 4 + (nb >> 5)] =
                        make_float2(p0, p1);
            }
        }
        if (tt == 0) __syncthreads();
    }
}

// ================= SIMT node GEMM (proven FFMA2 path) ==================
#define WS_FLOATS (HID * HID)
#define AS_PAD 132
#define AS_FLOATS (32 * AS_PAD)

__device__ __forceinline__ void load_W_smem(float* Wsm, const float* __restrict__ W, int tid) {
    const float4* Wv = (const float4*)W;
    float4* Wd = (float4*)Wsm;
#pragma unroll
    for (int i = 0; i < WS_FLOATS / 4 / 256; i++)
        Wd[tid + 256 * i] = Wv[tid + 256 * i];
}
__device__ __forceinline__ void loadA_regs(float4 pa[4], const float* __restrict__ A,
                                           int m0, int k0, int lr, int lc) {
#pragma unroll
    for (int i = 0; i < 4; i++) {
        int m = m0 + lr + 32 * i;
        if (m < NN)
            pa[i] = *(const float4*)&A[(size_t)m * HID + k0 + lc];
        else
            pa[i] = make_float4(0.f, 0.f, 0.f, 0.f);
    }
}
__device__ __forceinline__ void storeA_smem(float* As, const float4 pa[4], int lr, int lc) {
#pragma unroll
    for (int i = 0; i < 4; i++) {
        As[(lc + 0) * AS_PAD + lr + 32 * i] = pa[i].x;
        As[(lc + 1) * AS_PAD + lr + 32 * i] = pa[i].y;
        As[(lc + 2) * AS_PAD + lr + 32 * i] = pa[i].z;
        As[(lc + 3) * AS_PAD + lr + 32 * i] = pa[i].w;
    }
}
__device__ __forceinline__ void compute_chunk(unsigned long long acc2[8][4],
                                              const float* As, const float* Wsm,
                                              int k0, int tx, int ty) {
#pragma unroll 8
    for (int kk = 0; kk < 32; kk++) {
        float4 a0 = *(const float4*)&As[kk * AS_PAD + ty * 8];
        float4 a1 = *(const float4*)&As[kk * AS_PAD + ty * 8 + 4];
        float4 b0 = *(const float4*)&Wsm[(k0 + kk) * HID + tx * 8];
        float4 b1 = *(const float4*)&Wsm[(k0 + kk) * HID + tx * 8 + 4];
        unsigned long long bp[4] = {pack2(b0.x, b0.y), pack2(b0.z, b0.w),
                                    pack2(b1.x, b1.y), pack2(b1.z, b1.w)};
        float a[8] = {a0.x, a0.y, a0.z, a0.w, a1.x, a1.y, a1.z, a1.w};
#pragma unroll
        for (int i = 0; i < 8; i++) {
            unsigned long long ap = bcast2(a[i]);
#pragma unroll
            for (int j = 0; j < 4; j++) ffma2(acc2[i][j], ap, bp[j]);
        }
    }
}

__global__ __launch_bounds__(256, 2) void gemm_node(const float* __restrict__ Wl,
                                                    const float* __restrict__ bl,
                                                    const float* __restrict__ Wr,
                                                    const float* __restrict__ br) {
    extern __shared__ __align__(16) float smem[];
    float* Wsm = smem;
    float* As = smem + WS_FLOATS;

    const float* W    = blockIdx.y ? Wr : Wl;
    const float* bias = blockIdx.y ? br : bl;
    float* C          = blockIdx.y ? g_xr : g_xl;
    const float* A = g_h;

    int tid = threadIdx.x;
    int tx = tid & 15, ty = tid >> 4;
    int lr = tid >> 3, lc = (tid & 7) << 2;
    int m0 = blockIdx.x * 128;

    load_W_smem(Wsm, W, tid);

    unsigned long long acc2[8][4];
#pragma unroll
    for (int i = 0; i < 8; i++)
#pragma unroll
        for (int j = 0; j < 4; j++) acc2[i][j] = 0ull;

    float4 pa[4];
    loadA_regs(pa, A, m0, 0, lr, lc);
    storeA_smem(As, pa, lr, lc);
    __syncthreads();

#pragma unroll
    for (int c = 0; c < 4; c++) {
        if (c < 3) loadA_regs(pa, A, m0, (c + 1) * 32, lr, lc);
        compute_chunk(acc2, As, Wsm, c * 32, tx, ty);
        __syncthreads();
        if (c < 3) { storeA_smem(As, pa, lr, lc); __syncthreads(); }
    }

#pragma unroll
    for (int i = 0; i < 8; i++) {
        int m = m0 + ty * 8 + i;
        if (m < NN) {
#pragma unroll
            for (int jp = 0; jp < 4; jp += 2) {
                float2 p0 = *(float2*)&acc2[i][jp];
                float2 p1 = *(float2*)&acc2[i][jp + 1];
                int ccol = tx * 8 + jp * 2;
                float4 o;
                o.x = p0.x + __ldg(&bias[ccol + 0]);
                o.y = p0.y + __ldg(&bias[ccol + 1]);
                o.z = p1.x + __ldg(&bias[ccol + 2]);
                o.w = p1.y + __ldg(&bias[ccol + 3]);
                *(float4*)&C[(size_t)m * HID + ccol] = o;
            }
        }
    }
}

// ---------------- layer-0 node projection (K=12) ----------------
__global__ void node_proj12(const float* __restrict__ x,
                            const float* __restrict__ Wl, const float* __restrict__ bl,
                            const float* __restrict__ Wr, const float* __restrict__ br) {
    int idx = blockIdx.x * blockDim.x + threadIdx.x;
    int n = idx >> 7, j = idx & 127;
    float a = __ldg(&bl[j]);
    float b = __ldg(&br[j]);
#pragma unroll
    for (int k = 0; k < 12; k++) {
        float xv = __ldg(&x[n * 12 + k]);
        a = fmaf(xv, __ldg(&Wl[k * HID + j]), a);
        b = fmaf(xv, __ldg(&Wr[k * HID + j]), b);
    }
    g_xl[idx] = a;
    g_xr[idx] = b;
}

// ---------------- fused per-node: softmax + aggregate + bias + LN + SiLU (+res) ---
template <bool RES, bool LAST>
__global__ void node_fused_kernel(const float* __restrict__ gat_bias,
                                  const float* __restrict__ lng,
                                  const float* __restrict__ lnb,
                                  float* __restrict__ dout) {
    int n = blockIdx.x * 4 + (threadIdx.x >> 5);
    int lane = threadIdx.x & 31;
    if (n >= NN) return;
    int s0 = g_rowptr[n];
    int s1 = g_rowptr[n + 1];

    float mx = -3.4e38f;
    for (int p = s0 * 4 + lane; p < s1 * 4; p += 32) {
        int e = g_eids[p >> 2];
        mx = fmaxf(mx, g_score[(size_t)e * 4 + (p & 3)]);
    }
    mx = fmaxf(mx, __shfl_xor_sync(0xffffffffu, mx, 4));
    mx = fmaxf(mx, __shfl_xor_sync(0xffffffffu, mx, 8));
    mx = fmaxf(mx, __shfl_xor_sync(0xffffffffu, mx, 16));

    float den = 0.f;
    for (int p = s0 * 4 + lane; p < s1 * 4; p += 32) {
        int e = g_eids[p >> 2];
        den += __expf(g_score[(size_t)e * 4 + (p & 3)] - mx);
    }
    den += __shfl_xor_sync(0xffffffffu, den, 4);
    den += __shfl_xor_sync(0xffffffffu, den, 8);
    den += __shfl_xor_sync(0xffffffffu, den, 16);
    float inv = __fdividef(1.f, den + 1e-16f);

    float acc0 = 0.f, acc1 = 0.f, acc2 = 0.f, acc3 = 0.f;
    for (int i = s0; i < s1; i++) {
        int e = g_eids[i];
        int src = g_srcs[i];
        float a = 0.f;
        if (lane < 4) a = __expf(g_score[(size_t)e * 4 + lane] - mx) * inv;
        float al0 = __shfl_sync(0xffffffffu, a, 0);
        float al1 = __shfl_sync(0xffffffffu, a, 1);
        float al2 = __shfl_sync(0xffffffffu, a, 2);
        float al3 = __shfl_sync(0xffffffffu, a, 3);
        const float* xl = &g_xl[(size_t)src * HID];
        acc0 = fmaf(xl[0 * DH + lane], al0, acc0);
        acc1 = fmaf(xl[1 * DH + lane], al1, acc1);
        acc2 = fmaf(xl[2 * DH + lane], al2, acc2);
        acc3 = fmaf(xl[3 * DH + lane], al3, acc3);
    }

    float v0 = acc0 + __ldg(&gat_bias[0 * DH + lane]);
    float v1 = acc1 + __ldg(&gat_bias[1 * DH + lane]);
    float v2 = acc2 + __ldg(&gat_bias[2 * DH + lane]);
    float v3 = acc3 + __ldg(&gat_bias[3 * DH + lane]);

    float sm = v0 + v1 + v2 + v3;
#pragma unroll
    for (int off = 16; off; off >>= 1) sm += __shfl_xor_sync(0xffffffffu, sm, off);
    float mean = sm * (1.f / 128.f);
    float d0 = v0 - mean, d1 = v1 - mean, d2 = v2 - mean, d3 = v3 - mean;
    float sq = d0 * d0 + d1 * d1 + d2 * d2 + d3 * d3;
#pragma unroll
    for (int off = 16; off; off >>= 1) sq += __shfl_xor_sync(0xffffffffu, sq, off);
    float rstd = rsqrtf(sq * (1.f / 128.f) + 1e-5f);

#pragma unroll
    for (int h = 0; h < 4; h++) {
        int j = h * DH + lane;
        float d = (h == 0 ? d0 : h == 1 ? d1 : h == 2 ? d2 : d3);
        float t = fmaf(d * rstd, __ldg(&lng[j]), __ldg(&lnb[j]));
        float sil = fast_silu(t);
        float o = RES ? (g_h[n * HID + j] + sil) : sil;
        if (LAST) dout[n * HID + j] = o;
        else      g_h[n * HID + j] = o;
    }
}

// ---------------- launch ----------------
extern "C" void kernel_launch(void* const* d_in, const int* in_sizes, int n_in,
                              void* d_out, int out_size) {
    const float* x     = (const float*)d_in[0];
    const int*   ei    = (const int*)  d_in[1];
    const float* eattr = (const float*)d_in[2];
    const float* epw   = (const float*)d_in[3];
    const float* epb   = (const float*)d_in[4];
    const float* l0Wl  = (const float*)d_in[5];
    const float* l0bl  = (const float*)d_in[6];
    const float* l0Wr  = (const float*)d_in[7];
    const float* l0br  = (const float*)d_in[8];
    const float* l0We  = (const float*)d_in[9];
    const float* l0att = (const float*)d_in[10];
    const float* l0bias= (const float*)d_in[11];
    const float* Wl    = (const float*)d_in[12];
    const float* bl    = (const float*)d_in[13];
    const float* Wr    = (const float*)d_in[14];
    const float* br    = (const float*)d_in[15];
    const float* We    = (const float*)d_in[16];
    const float* att   = (const float*)d_in[17];
    const float* bias  = (const float*)d_in[18];
    const float* lng   = (const float*)d_in[19];
    const float* lnb   = (const float*)d_in[20];
    float* out = (float*)d_out;

    const int NODE_SMEM = (WS_FLOATS + AS_FLOATS) * 4;
    static bool attr_set = false;
    if (!attr_set) {
        cudaFuncSetAttribute(gemm_edge_score_mma,
                             cudaFuncAttributeMaxDynamicSharedMemorySize, ESM_BYTES);
        cudaFuncSetAttribute(gemm_node,
                             cudaFuncAttributeMaxDynamicSharedMemorySize, NODE_SMEM);
        attr_set = true;
    }

    // layer-0 prerequisites; edge GEMM kept at 4th launch for ncu capture
    eproj_kernel<<<(EE * 32) / 256, 256>>>(eattr, epw, epb);
    node_proj12<<<(NN * HID) / 256, 256>>>(x, l0Wl, l0bl, l0Wr, l0br);
    wprep_kernel<<<32, 256>>>(l0We);
    gemm_edge_score_mma<<<EE / 256, 256, ESM_BYTES>>>(l0att, ei);

    // CSR build
    zero_kernel<<<(NN + 255) / 256, 256>>>();
    hist_kernel<<<(EE + 255) / 256, 256>>>(ei);
    deg_block_sum<<<NBLK, 1024>>>();
    bsum_scan<<<1, 128>>>();
    rowptr_kernel<<<NBLK, 1024>>>();
    scatter_kernel<<<(EE + 255) / 256, 256>>>(ei);

    node_fused_kernel<false, false><<<NN / 4, 128>>>(l0bias, lng, lnb, nullptr);

    // layers 1..3 (residual)
    for (int i = 0; i < 3; i++) {
        dim3 ng((NN + 127) / 128, 2);
        gemm_node<<<ng, 256, NODE_SMEM>>>(Wl + i * HID * HID, bl + i * HID,
                                          Wr + i * HID * HID, br + i * HID);
        wprep_kernel<<<32, 256>>>(We + i * HID * HID);
        gemm_edge_score_mma<<<EE / 256, 256, ESM_BYTES>>>(att + i * HID, ei);
        if (i < 2)
            node_fused_kernel<true, false><<<NN / 4, 128>>>(
                bias + i * HID, lng + (i + 1) * HID, lnb + (i + 1) * HID, nullptr);
        else
            node_fused_kernel<true, true><<<NN / 4, 128>>>(
                bias + i * HID, lng + (i + 1) * HID, lnb + (i + 1) * HID, out);
    }
}

// round 10
// speedup vs baseline: 1.9195x; 1.0379x over previous
#include <cuda_runtime.h>
#include <cuda_bf16.h>
#include <math.h>
#include <stdint.h>

#define NN 100000
#define EE 800000
#define HID 128
#define NH 4
#define DH 32
#define NBLK ((NN + 1023) / 1024)   // 98
#define EPAD 68
#define TW (128 * EPAD)             // words per 128-row image (8704)
#define TB (TW * 4)                 // bytes per image (34816)
#define ESM_BYTES (4 * TB)          // Whi | Wlo | Ahi | Alo = 139264 B

// ---------------- scratch (static device globals; no allocation) ----------------
__device__ unsigned int g_Ahi[(size_t)EE * 64];   // edge feats bf16-hi pairs [e][kw]
__device__ unsigned int g_Alo[(size_t)EE * 64];
__device__ float g_xl[NN * HID];
__device__ float g_xr[NN * HID];
__device__ float g_h [NN * HID];
__device__ float g_score[EE * NH];                // CSR-position-indexed
__device__ unsigned int g_WhiE[8192], g_WloE[8192];
__device__ int g_deg[NN], g_cursor[NN], g_rowptr[NN + 1];
__device__ int g_eids[EE], g_srcs[EE], g_dsts[EE];
__device__ int g_bsum[NBLK], g_boff[NBLK];

// ---------------- helpers ----------------
__device__ __forceinline__ float fast_silu(float z) {
    return __fdividef(z, 1.0f + __expf(-z));
}
__device__ __forceinline__ unsigned int packbf2(float x, float y) {
    __nv_bfloat162 t = __floats2bfloat162_rn(x, y);
    return *(unsigned int*)&t;
}
__device__ __forceinline__ void bf_split(float x, float& hi, float& lo) {
    __nv_bfloat16 h = __float2bfloat16_rn(x);
    hi = __bfloat162float(h);
    lo = x - hi;
}
__device__ __forceinline__ void mma_bf16(float c[4],
                                         unsigned int a0, unsigned int a1,
                                         unsigned int a2, unsigned int a3,
                                         unsigned int b0, unsigned int b1) {
    asm volatile("mma.sync.aligned.m16n8k16.row.col.f32.bf16.bf16.f32 "
                 "{%0,%1,%2,%3}, {%4,%5,%6,%7}, {%8,%9}, {%0,%1,%2,%3};"
                 : "+f"(c[0]), "+f"(c[1]), "+f"(c[2]), "+f"(c[3])
                 : "r"(a0), "r"(a1), "r"(a2), "r"(a3), "r"(b0), "r"(b1));
}
// packed fp32x2 (FFMA2) for the node GEMM
__device__ __forceinline__ unsigned long long pack2(float x, float y) {
    unsigned long long r;
    asm("mov.b64 %0, {%1, %2};" : "=l"(r) : "f"(x), "f"(y));
    return r;
}
__device__ __forceinline__ unsigned long long bcast2(float x) {
    unsigned long long r;
    asm("mov.b64 %0, {%1, %1};" : "=l"(r) : "f"(x));
    return r;
}
__device__ __forceinline__ void ffma2(unsigned long long& d,
                                      unsigned long long a, unsigned long long b) {
    asm("fma.rn.f32x2 %0, %1, %2, %0;" : "+l"(d) : "l"(a), "l"(b));
}
__device__ __forceinline__ uint32_t smem_u32(const void* p) {
    uint32_t a;
    asm("{ .reg .u64 t; cvta.to.shared.u64 t, %1; cvt.u32.u64 %0, t; }" : "=r"(a) : "l"(p));
    return a;
}
__device__ __forceinline__ void cp16(uint32_t d, const void* s) {
    size_t gs = __cvta_generic_to_global((void*)s);
    asm volatile("cp.async.cg.shared.global [%0], [%1], 16;"
                 :: "r"(d), "l"((unsigned long long)gs) : "memory");
}
__device__ __forceinline__ void cp_commit() {
    asm volatile("cp.async.commit_group;" ::: "memory");
}
template <int N>
__device__ __forceinline__ void cp_wait() {
    asm volatile("cp.async.wait_group %0;" :: "n"(N) : "memory");
}

// ---------------- edge feature projection: bf16 hi/lo pair images ----------------
__global__ void eproj_kernel(const float* __restrict__ attr,
                             const float* __restrict__ W,
                             const float* __restrict__ b) {
    int idx = blockIdx.x * blockDim.x + threadIdx.x;   // E*32 threads
    int e = idx >> 5, c4 = (idx & 31) << 2;
    float a0 = __ldg(&attr[e * 3 + 0]);
    float a1 = __ldg(&attr[e * 3 + 1]);
    float a2 = __ldg(&attr[e * 3 + 2]);
    float v[4];
#pragma unroll
    for (int u = 0; u < 4; u++) {
        int j = c4 + u;
        float z = __ldg(&b[j]);
        z = fmaf(a0, __ldg(&W[j]),           z);
        z = fmaf(a1, __ldg(&W[HID + j]),     z);
        z = fmaf(a2, __ldg(&W[2 * HID + j]), z);
        v[u] = fast_silu(z);
    }
    float h0, l0, h1, l1, h2, l2, h3, l3;
    bf_split(v[0], h0, l0); bf_split(v[1], h1, l1);
    bf_split(v[2], h2, l2); bf_split(v[3], h3, l3);
    size_t base = (size_t)e * 64 + (c4 >> 1);
    *(uint2*)&g_Ahi[base] = make_uint2(packbf2(h0, h1), packbf2(h2, h3));
    *(uint2*)&g_Alo[base] = make_uint2(packbf2(l0, l1), packbf2(l2, l3));
}

// ---------------- CSR build (by dst) ----------------
__global__ void zero_kernel() {
    int i = blockIdx.x * blockDim.x + threadIdx.x;
    if (i < NN) { g_deg[i] = 0; g_cursor[i] = 0; }
}
__global__ void hist_kernel(const int* __restrict__ ei) {
    int e = blockIdx.x * blockDim.x + threadIdx.x;
    if (e < EE) atomicAdd(&g_deg[ei[EE + e]], 1);
}
__global__ void deg_block_sum() {
    __shared__ int sh[1024];
    int i = blockIdx.x * 1024 + threadIdx.x;
    sh[threadIdx.x] = (i < NN) ? g_deg[i] : 0;
    __syncthreads();
    for (int off = 512; off; off >>= 1) {
        if (threadIdx.x < off) sh[threadIdx.x] += sh[threadIdx.x + off];
        __syncthreads();
    }
    if (threadIdx.x == 0) g_bsum[blockIdx.x] = sh[0];
}
__global__ void bsum_scan() {
    __shared__ int sh[128];
    int t = threadIdx.x;
    int v = (t < NBLK) ? g_bsum[t] : 0;
    sh[t] = v;
    __syncthreads();
    for (int off = 1; off < 128; off <<= 1) {
        int u = (t >= off) ? sh[t - off] : 0;
        __syncthreads();
        sh[t] += u;
        __syncthreads();
    }
    if (t < NBLK) g_boff[t] = sh[t] - v;
}
__global__ void rowptr_kernel() {
    __shared__ int sh[1024];
    int i = blockIdx.x * 1024 + threadIdx.x;
    int v = (i < NN) ? g_deg[i] : 0;
    sh[threadIdx.x] = v;
    __syncthreads();
    for (int off = 1; off < 1024; off <<= 1) {
        int u = (threadIdx.x >= off) ? sh[threadIdx.x - off] : 0;
        __syncthreads();
        sh[threadIdx.x] += u;
        __syncthreads();
    }
    if (i < NN) g_rowptr[i + 1] = sh[threadIdx.x] + g_boff[blockIdx.x];
    if (i == 0) g_rowptr[0] = 0;
}
__global__ void scatter_kernel(const int* __restrict__ ei) {
    int e = blockIdx.x * blockDim.x + threadIdx.x;
    if (e < EE) {
        int src = ei[e];
        int d = ei[EE + e];
        int pos = g_rowptr[d] + atomicAdd(&g_cursor[d], 1);
        g_eids[pos] = e;
        g_srcs[pos] = src;
        g_dsts[pos] = d;
    }
}

// ---------------- W image prep (edge We) ----------------
__global__ void wprep_kernel(const float* __restrict__ W) {
    int idx = blockIdx.x * 256 + threadIdx.x;   // 8192
    int n = idx >> 6, kw = idx & 63;
    float w0 = __ldg(&W[(2 * kw) * HID + n]);
    float w1 = __ldg(&W[(2 * kw + 1) * HID + n]);
    float h0, l0, h1, l1;
    bf_split(w0, h0, l0);
    bf_split(w1, h1, l1);
    g_WhiE[idx] = packbf2(h0, h1);
    g_WloE[idx] = packbf2(l0, l1);
}

// ================= edge GEMM + fused score (CSR-ordered tiles) ==================
__global__ __launch_bounds__(256, 1) void gemm_edge_score_mma(
        const float* __restrict__ att) {
    extern __shared__ __align__(16) unsigned int esm[];
    // layout: Whi[TW] | Wlo[TW] | Ahi[TW] | Alo[TW]
    uint32_t sb = smem_u32(esm);
    int tid = threadIdx.x;
    int m0 = blockIdx.x * 128;   // CSR positions m0..m0+127

    // stage A (hi/lo) via cp.async with eid indirection (dst-sorted order)
#pragma unroll
    for (int i = 0; i < 8; i++) {
        int idx = i * 256 + tid;              // 2048 chunks
        int row = idx >> 4, c = (idx & 15) << 2;
        int eid = __ldg(&g_eids[m0 + row]);   // 16 threads share a row -> broadcast
        uint32_t doff = (uint32_t)(row * EPAD + c) * 4;
        cp16(sb + 2 * TB + doff, &g_Ahi[(size_t)eid * 64 + c]);
        cp16(sb + 3 * TB + doff, &g_Alo[(size_t)eid * 64 + c]);
    }
    cp_commit();

    // stage W (regular uint4 loads; L2-resident)
#pragma unroll
    for (int i = 0; i < 8; i++) {
        int idx = i * 256 + tid;              // 2048 uint4
        int n = idx >> 4, c = (idx & 15) << 2;
        uint4 vh = ((const uint4*)g_WhiE)[idx];
        uint4 vl = ((const uint4*)g_WloE)[idx];
        *(uint4*)&esm[n * EPAD + c] = vh;
        *(uint4*)&esm[TW + n * EPAD + c] = vl;
    }
    cp_wait<0>();
    __syncthreads();

    int wid = tid >> 5, lane = tid & 31, g = lane >> 2, q = lane & 3;
    int mb = (wid & 3) * 32;        // 4 row groups
    int nb = (wid >> 2) * 64;       // 2 col groups (2 heads each)

    float acc[2][8][4];
#pragma unroll
    for (int t = 0; t < 2; t++)
#pragma unroll
        for (int j = 0; j < 8; j++)
#pragma unroll
            for (int c = 0; c < 4; c++) acc[t][j][c] = 0.f;

    // 3 passes: (Ahi,Whi), (Ahi,Wlo), (Alo,Whi)
#pragma unroll
    for (int pass = 0; pass < 3; pass++) {
        const unsigned int* As = (pass == 2) ? esm + 3 * TW : esm + 2 * TW;
        const unsigned int* Bs = (pass == 1) ? esm + TW : esm;
#pragma unroll
        for (int ks = 0; ks < 8; ks++) {
            int kw0 = ks * 8 + q;
            unsigned int a[2][4];
#pragma unroll
            for (int t = 0; t < 2; t++) {
                int r = mb + 16 * t + g;
                a[t][0] = As[r * EPAD + kw0];
                a[t][1] = As[(r + 8) * EPAD + kw0];
                a[t][2] = As[r * EPAD + kw0 + 4];
                a[t][3] = As[(r + 8) * EPAD + kw0 + 4];
            }
            unsigned int b[8][2];
#pragma unroll
            for (int j = 0; j < 8; j++) {
                int n = nb + 8 * j + g;
                b[j][0] = Bs[n * EPAD + kw0];
                b[j][1] = Bs[n * EPAD + kw0 + 4];
            }
#pragma unroll
            for (int t = 0; t < 2; t++)
#pragma unroll
                for (int j = 0; j < 8; j++)
                    mma_bf16(acc[t][j], a[t][0], a[t][1], a[t][2], a[t][3],
                             b[j][0], b[j][1]);
        }
    }

    // fused epilogue; dst is sorted within the tile -> xr rows L1-shared
    float2 attv[8];
#pragma unroll
    for (int j = 0; j < 8; j++)
        attv[j] = *(const float2*)&att[nb + 8 * j + 2 * q];

#pragma unroll
    for (int t = 0; t < 2; t++) {
#pragma unroll
        for (int rr = 0; rr < 2; rr++) {
            int row = mb + 16 * t + 8 * rr + g;
            int pos = m0 + row;
            int src = __ldg(&g_srcs[pos]);
            int dst = __ldg(&g_dsts[pos]);
            const float* xlp = &g_xl[(size_t)src * HID];
            const float* xrp = &g_xr[(size_t)dst * HID];
            float p0 = 0.f, p1 = 0.f;
#pragma unroll
            for (int j = 0; j < 8; j++) {
                int cc = nb + 8 * j + 2 * q;
                float2 xl = *(const float2*)&xlp[cc];
                float2 xr = *(const float2*)&xrp[cc];
                float e0 = acc[t][j][rr * 2 + 0] + xl.x + xr.x;
                float e1 = acc[t][j][rr * 2 + 1] + xl.y + xr.y;
                e0 = (e0 > 0.f) ? e0 : 0.2f * e0;
                e1 = (e1 > 0.f) ? e1 : 0.2f * e1;
                float ps = fmaf(e0, attv[j].x, e1 * attv[j].y);
                if (j < 4) p0 += ps; else p1 += ps;
            }
            p0 += __shfl_xor_sync(0xffffffffu, p0, 1);
            p0 += __shfl_xor_sync(0xffffffffu, p0, 2);
            p1 += __shfl_xor_sync(0xffffffffu, p1, 1);
            p1 += __shfl_xor_sync(0xffffffffu, p1, 2);
            if (q == 0)
                *(float2*)&g_score[(size_t)pos * 4 + (nb >> 5)] =
                    make_float2(p0, p1);
        }
    }
}

// ================= SIMT node GEMM (proven FFMA2 path) ==================
#define WS_FLOATS (HID * HID)
#define AS_PAD 132
#define AS_FLOATS (32 * AS_PAD)

__device__ __forceinline__ void load_W_smem(float* Wsm, const float* __restrict__ W, int tid) {
    const float4* Wv = (const float4*)W;
    float4* Wd = (float4*)Wsm;
#pragma unroll
    for (int i = 0; i < WS_FLOATS / 4 / 256; i++)
        Wd[tid + 256 * i] = Wv[tid + 256 * i];
}
__device__ __forceinline__ void loadA_regs(float4 pa[4], const float* __restrict__ A,
                                           int m0, int k0, int lr, int lc) {
#pragma unroll
    for (int i = 0; i < 4; i++) {
        int m = m0 + lr + 32 * i;
        if (m < NN)
            pa[i] = *(const float4*)&A[(size_t)m * HID + k0 + lc];
        else
            pa[i] = make_float4(0.f, 0.f, 0.f, 0.f);
    }
}
__device__ __forceinline__ void storeA_smem(float* As, const float4 pa[4], int lr, int lc) {
#pragma unroll
    for (int i = 0; i < 4; i++) {
        As[(lc + 0) * AS_PAD + lr + 32 * i] = pa[i].x;
        As[(lc + 1) * AS_PAD + lr + 32 * i] = pa[i].y;
        As[(lc + 2) * AS_PAD + lr + 32 * i] = pa[i].z;
        As[(lc + 3) * AS_PAD + lr + 32 * i] = pa[i].w;
    }
}
__device__ __forceinline__ void compute_chunk(unsigned long long acc2[8][4],
                                              const float* As, const float* Wsm,
                                              int k0, int tx, int ty) {
#pragma unroll 8
    for (int kk = 0; kk < 32; kk++) {
        float4 a0 = *(const float4*)&As[kk * AS_PAD + ty * 8];
        float4 a1 = *(const float4*)&As[kk * AS_PAD + ty * 8 + 4];
        float4 b0 = *(const float4*)&Wsm[(k0 + kk) * HID + tx * 8];
        float4 b1 = *(const float4*)&Wsm[(k0 + kk) * HID + tx * 8 + 4];
        unsigned long long bp[4] = {pack2(b0.x, b0.y), pack2(b0.z, b0.w),
                                    pack2(b1.x, b1.y), pack2(b1.z, b1.w)};
        float a[8] = {a0.x, a0.y, a0.z, a0.w, a1.x, a1.y, a1.z, a1.w};
#pragma unroll
        for (int i = 0; i < 8; i++) {
            unsigned long long ap = bcast2(a[i]);
#pragma unroll
            for (int j = 0; j < 4; j++) ffma2(acc2[i][j], ap, bp[j]);
        }
    }
}

__global__ __launch_bounds__(256, 2) void gemm_node(const float* __restrict__ Wl,
                                                    const float* __restrict__ bl,
                                                    const float* __restrict__ Wr,
                                                    const float* __restrict__ br) {
    extern __shared__ __align__(16) float smem[];
    float* Wsm = smem;
    float* As = smem + WS_FLOATS;

    const float* W    = blockIdx.y ? Wr : Wl;
    const float* bias = blockIdx.y ? br : bl;
    float* C          = blockIdx.y ? g_xr : g_xl;
    const float* A = g_h;

    int tid = threadIdx.x;
    int tx = tid & 15, ty = tid >> 4;
    int lr = tid >> 3, lc = (tid & 7) << 2;
    int m0 = blockIdx.x * 128;

    load_W_smem(Wsm, W, tid);

    unsigned long long acc2[8][4];
#pragma unroll
    for (int i = 0; i < 8; i++)
#pragma unroll
        for (int j = 0; j < 4; j++) acc2[i][j] = 0ull;

    float4 pa[4];
    loadA_regs(pa, A, m0, 0, lr, lc);
    storeA_smem(As, pa, lr, lc);
    __syncthreads();

#pragma unroll
    for (int c = 0; c < 4; c++) {
        if (c < 3) loadA_regs(pa, A, m0, (c + 1) * 32, lr, lc);
        compute_chunk(acc2, As, Wsm, c * 32, tx, ty);
        __syncthreads();
        if (c < 3) { storeA_smem(As, pa, lr, lc); __syncthreads(); }
    }

#pragma unroll
    for (int i = 0; i < 8; i++) {
        int m = m0 + ty * 8 + i;
        if (m < NN) {
#pragma unroll
            for (int jp = 0; jp < 4; jp += 2) {
                float2 p0 = *(float2*)&acc2[i][jp];
                float2 p1 = *(float2*)&acc2[i][jp + 1];
                int ccol = tx * 8 + jp * 2;
                float4 o;
                o.x = p0.x + __ldg(&bias[ccol + 0]);
                o.y = p0.y + __ldg(&bias[ccol + 1]);
                o.z = p1.x + __ldg(&bias[ccol + 2]);
                o.w = p1.y + __ldg(&bias[ccol + 3]);
                *(float4*)&C[(size_t)m * HID + ccol] = o;
            }
        }
    }
}

// ---------------- layer-0 node projection (K=12) ----------------
__global__ void node_proj12(const float* __restrict__ x,
                            const float* __restrict__ Wl, const float* __restrict__ bl,
                            const float* __restrict__ Wr, const float* __restrict__ br) {
    int idx = blockIdx.x * blockDim.x + threadIdx.x;
    int n = idx >> 7, j = idx & 127;
    float a = __ldg(&bl[j]);
    float b = __ldg(&br[j]);
#pragma unroll
    for (int k = 0; k < 12; k++) {
        float xv = __ldg(&x[n * 12 + k]);
        a = fmaf(xv, __ldg(&Wl[k * HID + j]), a);
        b = fmaf(xv, __ldg(&Wr[k * HID + j]), b);
    }
    g_xl[idx] = a;
    g_xr[idx] = b;
}

// ------- fused per-node: softmax + aggregate + bias + LN + SiLU (+res) ----------
// Scores are CSR-position-indexed -> all score reads are sequential.
template <bool RES, bool LAST>
__global__ void node_fused_kernel(const float* __restrict__ gat_bias,
                                  const float* __restrict__ lng,
                                  const float* __restrict__ lnb,
                                  float* __restrict__ dout) {
    int n = blockIdx.x * 4 + (threadIdx.x >> 5);
    int lane = threadIdx.x & 31;
    if (n >= NN) return;
    int s0 = g_rowptr[n];
    int s1 = g_rowptr[n + 1];

    float mx = -3.4e38f;
    for (int p = s0 * 4 + lane; p < s1 * 4; p += 32)
        mx = fmaxf(mx, g_score[p]);
    mx = fmaxf(mx, __shfl_xor_sync(0xffffffffu, mx, 4));
    mx = fmaxf(mx, __shfl_xor_sync(0xffffffffu, mx, 8));
    mx = fmaxf(mx, __shfl_xor_sync(0xffffffffu, mx, 16));

    float den = 0.f;
    for (int p = s0 * 4 + lane; p < s1 * 4; p += 32)
        den += __expf(g_score[p] - mx);
    den += __shfl_xor_sync(0xffffffffu, den, 4);
    den += __shfl_xor_sync(0xffffffffu, den, 8);
    den += __shfl_xor_sync(0xffffffffu, den, 16);
    float inv = __fdividef(1.f, den + 1e-16f);

    float acc0 = 0.f, acc1 = 0.f, acc2 = 0.f, acc3 = 0.f;
    for (int i = s0; i < s1; i++) {
        int src = g_srcs[i];
        float a = 0.f;
        if (lane < 4) a = __expf(g_score[(size_t)i * 4 + lane] - mx) * inv;
        float al0 = __shfl_sync(0xffffffffu, a, 0);
        float al1 = __shfl_sync(0xffffffffu, a, 1);
        float al2 = __shfl_sync(0xffffffffu, a, 2);
        float al3 = __shfl_sync(0xffffffffu, a, 3);
        const float* xl = &g_xl[(size_t)src * HID];
        acc0 = fmaf(xl[0 * DH + lane], al0, acc0);
        acc1 = fmaf(xl[1 * DH + lane], al1, acc1);
        acc2 = fmaf(xl[2 * DH + lane], al2, acc2);
        acc3 = fmaf(xl[3 * DH + lane], al3, acc3);
    }

    float v0 = acc0 + __ldg(&gat_bias[0 * DH + lane]);
    float v1 = acc1 + __ldg(&gat_bias[1 * DH + lane]);
    float v2 = acc2 + __ldg(&gat_bias[2 * DH + lane]);
    float v3 = acc3 + __ldg(&gat_bias[3 * DH + lane]);

    float sm = v0 + v1 + v2 + v3;
#pragma unroll
    for (int off = 16; off; off >>= 1) sm += __shfl_xor_sync(0xffffffffu, sm, off);
    float mean = sm * (1.f / 128.f);
    float d0 = v0 - mean, d1 = v1 - mean, d2 = v2 - mean, d3 = v3 - mean;
    float sq = d0 * d0 + d1 * d1 + d2 * d2 + d3 * d3;
#pragma unroll
    for (int off = 16; off; off >>= 1) sq += __shfl_xor_sync(0xffffffffu, sq, off);
    float rstd = rsqrtf(sq * (1.f / 128.f) + 1e-5f);

#pragma unroll
    for (int h = 0; h < 4; h++) {
        int j = h * DH + lane;
        float d = (h == 0 ? d0 : h == 1 ? d1 : h == 2 ? d2 : d3);
        float t = fmaf(d * rstd, __ldg(&lng[j]), __ldg(&lnb[j]));
        float sil = fast_silu(t);
        float o = RES ? (g_h[n * HID + j] + sil) : sil;
        if (LAST) dout[n * HID + j] = o;
        else      g_h[n * HID + j] = o;
    }
}

// ---------------- launch ----------------
extern "C" void kernel_launch(void* const* d_in, const int* in_sizes, int n_in,
                              void* d_out, int out_size) {
    const float* x     = (const float*)d_in[0];
    const int*   ei    = (const int*)  d_in[1];
    const float* eattr = (const float*)d_in[2];
    const float* epw   = (const float*)d_in[3];
    const float* epb   = (const float*)d_in[4];
    const float* l0Wl  = (const float*)d_in[5];
    const float* l0bl  = (const float*)d_in[6];
    const float* l0Wr  = (const float*)d_in[7];
    const float* l0br  = (const float*)d_in[8];
    const float* l0We  = (const float*)d_in[9];
    const float* l0att = (const float*)d_in[10];
    const float* l0bias= (const float*)d_in[11];
    const float* Wl    = (const float*)d_in[12];
    const float* bl    = (const float*)d_in[13];
    const float* Wr    = (const float*)d_in[14];
    const float* br    = (const float*)d_in[15];
    const float* We    = (const float*)d_in[16];
    const float* att   = (const float*)d_in[17];
    const float* bias  = (const float*)d_in[18];
    const float* lng   = (const float*)d_in[19];
    const float* lnb   = (const float*)d_in[20];
    float* out = (float*)d_out;

    const int NODE_SMEM = (WS_FLOATS + AS_FLOATS) * 4;
    static bool attr_set = false;
    if (!attr_set) {
        cudaFuncSetAttribute(gemm_edge_score_mma,
                             cudaFuncAttributeMaxDynamicSharedMemorySize, ESM_BYTES);
        cudaFuncSetAttribute(gemm_node,
                             cudaFuncAttributeMaxDynamicSharedMemorySize, NODE_SMEM);
        attr_set = true;
    }

    // independent prep
    eproj_kernel<<<(EE * 32) / 256, 256>>>(eattr, epw, epb);
    node_proj12<<<(NN * HID) / 256, 256>>>(x, l0Wl, l0bl, l0Wr, l0br);
    wprep_kernel<<<32, 256>>>(l0We);

    // CSR build (must precede the first edge GEMM)
    zero_kernel<<<(NN + 255) / 256, 256>>>();
    hist_kernel<<<(EE + 255) / 256, 256>>>(ei);
    deg_block_sum<<<NBLK, 1024>>>();
    bsum_scan<<<1, 128>>>();
    rowptr_kernel<<<NBLK, 1024>>>();
    scatter_kernel<<<(EE + 255) / 256, 256>>>(ei);

    // layer 0
    gemm_edge_score_mma<<<EE / 128, 256, ESM_BYTES>>>(l0att);
    node_fused_kernel<false, false><<<NN / 4, 128>>>(l0bias, lng, lnb, nullptr);

    // layers 1..3 (residual)
    for (int i = 0; i < 3; i++) {
        dim3 ng((NN + 127) / 128, 2);
        gemm_node<<<ng, 256, NODE_SMEM>>>(Wl + i * HID * HID, bl + i * HID,
                                          Wr + i * HID * HID, br + i * HID);
        wprep_kernel<<<32, 256>>>(We + i * HID * HID);
        gemm_edge_score_mma<<<EE / 128, 256, ESM_BYTES>>>(att + i * HID);
        if (i < 2)
            node_fused_kernel<true, false><<<NN / 4, 128>>>(
                bias + i * HID, lng + (i + 1) * HID, lnb + (i + 1) * HID, nullptr);
        else
            node_fused_kernel<true, true><<<NN / 4, 128>>>(
                bias + i * HID, lng + (i + 1) * HID, lnb + (i + 1) * HID, out);
    }
}

// round 11
// speedup vs baseline: 1.9584x; 1.0202x over previous
#include <cuda_runtime.h>
#include <cuda_bf16.h>
#include <math.h>
#include <stdint.h>

#define NN 100000
#define EE 800000
#define HID 128
#define NH 4
#define DH 32
#define NBLK ((NN + 1023) / 1024)   // 98
#define EPAD 68
#define TW (128 * EPAD)             // words per 128-row image (8704)
#define TB (TW * 4)                 // bytes per image (34816)
#define ESM_BYTES (4 * TB)          // Whi | Wlo | Ahi | Alo = 139264 B
#define XLPAD 132                   // xl prefetch row stride (floats); 528B, 16B-aligned

// ---------------- scratch (static device globals; no allocation) ----------------
__device__ unsigned int g_Ahi[(size_t)EE * 64];   // edge feats bf16-hi pairs [e][kw]
__device__ unsigned int g_Alo[(size_t)EE * 64];
__device__ float g_xl[NN * HID];
__device__ float g_xr[NN * HID];
__device__ float g_h [NN * HID];
__device__ float g_score[EE * NH];                // CSR-position-indexed
__device__ unsigned int g_WhiE[8192], g_WloE[8192];
__device__ int g_deg[NN], g_cursor[NN], g_rowptr[NN + 1];
__device__ int g_eids[EE], g_srcs[EE], g_dsts[EE];
__device__ int g_bsum[NBLK], g_boff[NBLK];

// ---------------- helpers ----------------
__device__ __forceinline__ float fast_silu(float z) {
    return __fdividef(z, 1.0f + __expf(-z));
}
__device__ __forceinline__ unsigned int packbf2(float x, float y) {
    __nv_bfloat162 t = __floats2bfloat162_rn(x, y);
    return *(unsigned int*)&t;
}
__device__ __forceinline__ void bf_split(float x, float& hi, float& lo) {
    __nv_bfloat16 h = __float2bfloat16_rn(x);
    hi = __bfloat162float(h);
    lo = x - hi;
}
__device__ __forceinline__ void mma_bf16(float c[4],
                                         unsigned int a0, unsigned int a1,
                                         unsigned int a2, unsigned int a3,
                                         unsigned int b0, unsigned int b1) {
    asm volatile("mma.sync.aligned.m16n8k16.row.col.f32.bf16.bf16.f32 "
                 "{%0,%1,%2,%3}, {%4,%5,%6,%7}, {%8,%9}, {%0,%1,%2,%3};"
                 : "+f"(c[0]), "+f"(c[1]), "+f"(c[2]), "+f"(c[3])
                 : "r"(a0), "r"(a1), "r"(a2), "r"(a3), "r"(b0), "r"(b1));
}
// packed fp32x2 (FFMA2) for the node GEMM
__device__ __forceinline__ unsigned long long pack2(float x, float y) {
    unsigned long long r;
    asm("mov.b64 %0, {%1, %2};" : "=l"(r) : "f"(x), "f"(y));
    return r;
}
__device__ __forceinline__ unsigned long long bcast2(float x) {
    unsigned long long r;
    asm("mov.b64 %0, {%1, %1};" : "=l"(r) : "f"(x));
    return r;
}
__device__ __forceinline__ void ffma2(unsigned long long& d,
                                      unsigned long long a, unsigned long long b) {
    asm("fma.rn.f32x2 %0, %1, %2, %0;" : "+l"(d) : "l"(a), "l"(b));
}
__device__ __forceinline__ uint32_t smem_u32(const void* p) {
    uint32_t a;
    asm("{ .reg .u64 t; cvta.to.shared.u64 t, %1; cvt.u32.u64 %0, t; }" : "=r"(a) : "l"(p));
    return a;
}
__device__ __forceinline__ void cp16(uint32_t d, const void* s) {
    size_t gs = __cvta_generic_to_global((void*)s);
    asm volatile("cp.async.cg.shared.global [%0], [%1], 16;"
                 :: "r"(d), "l"((unsigned long long)gs) : "memory");
}
__device__ __forceinline__ void cp_commit() {
    asm volatile("cp.async.commit_group;" ::: "memory");
}
template <int N>
__device__ __forceinline__ void cp_wait() {
    asm volatile("cp.async.wait_group %0;" :: "n"(N) : "memory");
}

// ---------------- edge feature projection: bf16 hi/lo pair images ----------------
__global__ void eproj_kernel(const float* __restrict__ attr,
                             const float* __restrict__ W,
                             const float* __restrict__ b) {
    int idx = blockIdx.x * blockDim.x + threadIdx.x;   // E*32 threads
    int e = idx >> 5, c4 = (idx & 31) << 2;
    float a0 = __ldg(&attr[e * 3 + 0]);
    float a1 = __ldg(&attr[e * 3 + 1]);
    float a2 = __ldg(&attr[e * 3 + 2]);
    float v[4];
#pragma unroll
    for (int u = 0; u < 4; u++) {
        int j = c4 + u;
        float z = __ldg(&b[j]);
        z = fmaf(a0, __ldg(&W[j]),           z);
        z = fmaf(a1, __ldg(&W[HID + j]),     z);
        z = fmaf(a2, __ldg(&W[2 * HID + j]), z);
        v[u] = fast_silu(z);
    }
    float h0, l0, h1, l1, h2, l2, h3, l3;
    bf_split(v[0], h0, l0); bf_split(v[1], h1, l1);
    bf_split(v[2], h2, l2); bf_split(v[3], h3, l3);
    size_t base = (size_t)e * 64 + (c4 >> 1);
    *(uint2*)&g_Ahi[base] = make_uint2(packbf2(h0, h1), packbf2(h2, h3));
    *(uint2*)&g_Alo[base] = make_uint2(packbf2(l0, l1), packbf2(l2, l3));
}

// ---------------- CSR build (by dst) ----------------
__global__ void zero_kernel() {
    int i = blockIdx.x * blockDim.x + threadIdx.x;
    if (i < NN) { g_deg[i] = 0; g_cursor[i] = 0; }
}
__global__ void hist_kernel(const int* __restrict__ ei) {
    int e = blockIdx.x * blockDim.x + threadIdx.x;
    if (e < EE) atomicAdd(&g_deg[ei[EE + e]], 1);
}
__global__ void deg_block_sum() {
    __shared__ int sh[1024];
    int i = blockIdx.x * 1024 + threadIdx.x;
    sh[threadIdx.x] = (i < NN) ? g_deg[i] : 0;
    __syncthreads();
    for (int off = 512; off; off >>= 1) {
        if (threadIdx.x < off) sh[threadIdx.x] += sh[threadIdx.x + off];
        __syncthreads();
    }
    if (threadIdx.x == 0) g_bsum[blockIdx.x] = sh[0];
}
__global__ void bsum_scan() {
    __shared__ int sh[128];
    int t = threadIdx.x;
    int v = (t < NBLK) ? g_bsum[t] : 0;
    sh[t] = v;
    __syncthreads();
    for (int off = 1; off < 128; off <<= 1) {
        int u = (t >= off) ? sh[t - off] : 0;
        __syncthreads();
        sh[t] += u;
        __syncthreads();
    }
    if (t < NBLK) g_boff[t] = sh[t] - v;
}
__global__ void rowptr_kernel() {
    __shared__ int sh[1024];
    int i = blockIdx.x * 1024 + threadIdx.x;
    int v = (i < NN) ? g_deg[i] : 0;
    sh[threadIdx.x] = v;
    __syncthreads();
    for (int off = 1; off < 1024; off <<= 1) {
        int u = (threadIdx.x >= off) ? sh[threadIdx.x - off] : 0;
        __syncthreads();
        sh[threadIdx.x] += u;
        __syncthreads();
    }
    if (i < NN) g_rowptr[i + 1] = sh[threadIdx.x] + g_boff[blockIdx.x];
    if (i == 0) g_rowptr[0] = 0;
}
__global__ void scatter_kernel(const int* __restrict__ ei) {
    int e = blockIdx.x * blockDim.x + threadIdx.x;
    if (e < EE) {
        int src = ei[e];
        int d = ei[EE + e];
        int pos = g_rowptr[d] + atomicAdd(&g_cursor[d], 1);
        g_eids[pos] = e;
        g_srcs[pos] = src;
        g_dsts[pos] = d;
    }
}

// ---------------- W image prep (edge We) ----------------
__global__ void wprep_kernel(const float* __restrict__ W) {
    int idx = blockIdx.x * 256 + threadIdx.x;   // 8192
    int n = idx >> 6, kw = idx & 63;
    float w0 = __ldg(&W[(2 * kw) * HID + n]);
    float w1 = __ldg(&W[(2 * kw + 1) * HID + n]);
    float h0, l0, h1, l1;
    bf_split(w0, h0, l0);
    bf_split(w1, h1, l1);
    g_WhiE[idx] = packbf2(h0, h1);
    g_WloE[idx] = packbf2(l0, l1);
}

// ---- one bf16 mma pass over the tile (8 K-steps) ----
__device__ __forceinline__ void pass_mma(float acc[2][8][4],
                                         const unsigned int* As,
                                         const unsigned int* Bs,
                                         int mb, int nb, int g, int q) {
#pragma unroll
    for (int ks = 0; ks < 8; ks++) {
        int kw0 = ks * 8 + q;
        unsigned int a[2][4];
#pragma unroll
        for (int t = 0; t < 2; t++) {
            int r = mb + 16 * t + g;
            a[t][0] = As[r * EPAD + kw0];
            a[t][1] = As[(r + 8) * EPAD + kw0];
            a[t][2] = As[r * EPAD + kw0 + 4];
            a[t][3] = As[(r + 8) * EPAD + kw0 + 4];
        }
        unsigned int b[8][2];
#pragma unroll
        for (int j = 0; j < 8; j++) {
            int n = nb + 8 * j + g;
            b[j][0] = Bs[n * EPAD + kw0];
            b[j][1] = Bs[n * EPAD + kw0 + 4];
        }
#pragma unroll
        for (int t = 0; t < 2; t++)
#pragma unroll
            for (int j = 0; j < 8; j++)
                mma_bf16(acc[t][j], a[t][0], a[t][1], a[t][2], a[t][3],
                         b[j][0], b[j][1]);
    }
}

// ---- prefetch 64 xl rows (CSR positions p0..p0+63) into a dead smem image ----
__device__ __forceinline__ void prefetch_xl(uint32_t dstbase, int p0, int tid) {
#pragma unroll
    for (int i = 0; i < 8; i++) {
        int idx = i * 256 + tid;              // 2048 chunks of 16B
        int row = idx >> 5;                   // 0..63
        int c = (idx & 31) << 2;              // float col 0..124
        int src = __ldg(&g_srcs[p0 + row]);   // 32 threads/row -> broadcast
        cp16(dstbase + (uint32_t)(row * XLPAD + c) * 4,
             &g_xl[(size_t)src * HID + c]);
    }
    cp_commit();
}

// ================= edge GEMM + fused score (CSR tiles, xl prefetch) =============
__global__ __launch_bounds__(256, 1) void gemm_edge_score_mma(
        const float* __restrict__ att) {
    extern __shared__ __align__(16) unsigned int esm[];
    // layout: Whi[TW] | Wlo[TW] | Ahi[TW] | Alo[TW]
    uint32_t sb = smem_u32(esm);
    int tid = threadIdx.x;
    int m0 = blockIdx.x * 128;   // CSR positions m0..m0+127

    // stage A (hi/lo) via cp.async with eid indirection (dst-sorted order)
#pragma unroll
    for (int i = 0; i < 8; i++) {
        int idx = i * 256 + tid;              // 2048 chunks
        int row = idx >> 4, c = (idx & 15) << 2;
        int eid = __ldg(&g_eids[m0 + row]);
        uint32_t doff = (uint32_t)(row * EPAD + c) * 4;
        cp16(sb + 2 * TB + doff, &g_Ahi[(size_t)eid * 64 + c]);
        cp16(sb + 3 * TB + doff, &g_Alo[(size_t)eid * 64 + c]);
    }
    cp_commit();

    // stage W (regular uint4 loads; L2-resident)
#pragma unroll
    for (int i = 0; i < 8; i++) {
        int idx = i * 256 + tid;
        int n = idx >> 4, c = (idx & 15) << 2;
        uint4 vh = ((const uint4*)g_WhiE)[idx];
        uint4 vl = ((const uint4*)g_WloE)[idx];
        *(uint4*)&esm[n * EPAD + c] = vh;
        *(uint4*)&esm[TW + n * EPAD + c] = vl;
    }
    cp_wait<0>();
    __syncthreads();

    int wid = tid >> 5, lane = tid & 31, g = lane >> 2, q = lane & 3;
    int mb = (wid & 3) * 32;        // 4 row groups
    int nb = (wid >> 2) * 64;       // 2 col groups (2 heads each)

    float acc[2][8][4];
#pragma unroll
    for (int t = 0; t < 2; t++)
#pragma unroll
        for (int j = 0; j < 8; j++)
#pragma unroll
            for (int c = 0; c < 4; c++) acc[t][j][c] = 0.f;

    // pass 0: (Alo, Whi) — frees Alo afterwards
    pass_mma(acc, esm + 3 * TW, esm, mb, nb, g, q);
    __syncthreads();
    prefetch_xl(sb + 3 * TB, m0, tid);          // xl rows 0..63 -> Alo space

    // pass 1: (Ahi, Wlo) — frees Wlo afterwards (cp.async overlaps)
    pass_mma(acc, esm + 2 * TW, esm + TW, mb, nb, g, q);
    __syncthreads();
    prefetch_xl(sb + 1 * TB, m0 + 64, tid);     // xl rows 64..127 -> Wlo space

    // pass 2: (Ahi, Whi) (cp.async overlaps)
    pass_mma(acc, esm + 2 * TW, esm, mb, nb, g, q);
    cp_wait<0>();
    __syncthreads();

    // fused epilogue: xl from smem, xr via L1 (dst-sorted reuse)
    const float* xlb0 = (const float*)(esm + 3 * TW);
    const float* xlb1 = (const float*)(esm + 1 * TW);
    float2 attv[8];
#pragma unroll
    for (int j = 0; j < 8; j++)
        attv[j] = *(const float2*)&att[nb + 8 * j + 2 * q];

#pragma unroll
    for (int t = 0; t < 2; t++) {
#pragma unroll
        for (int rr = 0; rr < 2; rr++) {
            int row = mb + 16 * t + 8 * rr + g;
            int pos = m0 + row;
            int dst = __ldg(&g_dsts[pos]);
            const float* xlp = (row < 64) ? (xlb0 + row * XLPAD)
                                          : (xlb1 + (row - 64) * XLPAD);
            const float* xrp = &g_xr[(size_t)dst * HID];
            float p0 = 0.f, p1 = 0.f;
#pragma unroll
            for (int j = 0; j < 8; j++) {
                int cc = nb + 8 * j + 2 * q;
                float2 xl = *(const float2*)&xlp[cc];
                float2 xr = *(const float2*)&xrp[cc];
                float e0 = acc[t][j][rr * 2 + 0] + xl.x + xr.x;
                float e1 = acc[t][j][rr * 2 + 1] + xl.y + xr.y;
                e0 = (e0 > 0.f) ? e0 : 0.2f * e0;
                e1 = (e1 > 0.f) ? e1 : 0.2f * e1;
                float ps = fmaf(e0, attv[j].x, e1 * attv[j].y);
                if (j < 4) p0 += ps; else p1 += ps;
            }
            p0 += __shfl_xor_sync(0xffffffffu, p0, 1);
            p0 += __shfl_xor_sync(0xffffffffu, p0, 2);
            p1 += __shfl_xor_sync(0xffffffffu, p1, 1);
            p1 += __shfl_xor_sync(0xffffffffu, p1, 2);
            if (q == 0)
                *(float2*)&g_score[(size_t)pos * 4 + (nb >> 5)] =
                    make_float2(p0, p1);
        }
    }
}

// ================= SIMT node GEMM (proven FFMA2 path) ==================
#define WS_FLOATS (HID * HID)
#define AS_PAD 132
#define AS_FLOATS (32 * AS_PAD)

__device__ __forceinline__ void load_W_smem(float* Wsm, const float* __restrict__ W, int tid) {
    const float4* Wv = (const float4*)W;
    float4* Wd = (float4*)Wsm;
#pragma unroll
    for (int i = 0; i < WS_FLOATS / 4 / 256; i++)
        Wd[tid + 256 * i] = Wv[tid + 256 * i];
}
__device__ __forceinline__ void loadA_regs(float4 pa[4], const float* __restrict__ A,
                                           int m0, int k0, int lr, int lc) {
#pragma unroll
    for (int i = 0; i < 4; i++) {
        int m = m0 + lr + 32 * i;
        if (m < NN)
            pa[i] = *(const float4*)&A[(size_t)m * HID + k0 + lc];
        else
            pa[i] = make_float4(0.f, 0.f, 0.f, 0.f);
    }
}
__device__ __forceinline__ void storeA_smem(float* As, const float4 pa[4], int lr, int lc) {
#pragma unroll
    for (int i = 0; i < 4; i++) {
        As[(lc + 0) * AS_PAD + lr + 32 * i] = pa[i].x;
        As[(lc + 1) * AS_PAD + lr + 32 * i] = pa[i].y;
        As[(lc + 2) * AS_PAD + lr + 32 * i] = pa[i].z;
        As[(lc + 3) * AS_PAD + lr + 32 * i] = pa[i].w;
    }
}
__device__ __forceinline__ void compute_chunk(unsigned long long acc2[8][4],
                                              const float* As, const float* Wsm,
                                              int k0, int tx, int ty) {
#pragma unroll 8
    for (int kk = 0; kk < 32; kk++) {
        float4 a0 = *(const float4*)&As[kk * AS_PAD + ty * 8];
        float4 a1 = *(const float4*)&As[kk * AS_PAD + ty * 8 + 4];
        float4 b0 = *(const float4*)&Wsm[(k0 + kk) * HID + tx * 8];
        float4 b1 = *(const float4*)&Wsm[(k0 + kk) * HID + tx * 8 + 4];
        unsigned long long bp[4] = {pack2(b0.x, b0.y), pack2(b0.z, b0.w),
                                    pack2(b1.x, b1.y), pack2(b1.z, b1.w)};
        float a[8] = {a0.x, a0.y, a0.z, a0.w, a1.x, a1.y, a1.z, a1.w};
#pragma unroll
        for (int i = 0; i < 8; i++) {
            unsigned long long ap = bcast2(a[i]);
#pragma unroll
            for (int j = 0; j < 4; j++) ffma2(acc2[i][j], ap, bp[j]);
        }
    }
}

__global__ __launch_bounds__(256, 2) void gemm_node(const float* __restrict__ Wl,
                                                    const float* __restrict__ bl,
                                                    const float* __restrict__ Wr,
                                                    const float* __restrict__ br) {
    extern __shared__ __align__(16) float smem[];
    float* Wsm = smem;
    float* As = smem + WS_FLOATS;

    const float* W    = blockIdx.y ? Wr : Wl;
    const float* bias = blockIdx.y ? br : bl;
    float* C          = blockIdx.y ? g_xr : g_xl;
    const float* A = g_h;

    int tid = threadIdx.x;
    int tx = tid & 15, ty = tid >> 4;
    int lr = tid >> 3, lc = (tid & 7) << 2;
    int m0 = blockIdx.x * 128;

    load_W_smem(Wsm, W, tid);

    unsigned long long acc2[8][4];
#pragma unroll
    for (int i = 0; i < 8; i++)
#pragma unroll
        for (int j = 0; j < 4; j++) acc2[i][j] = 0ull;

    float4 pa[4];
    loadA_regs(pa, A, m0, 0, lr, lc);
    storeA_smem(As, pa, lr, lc);
    __syncthreads();

#pragma unroll
    for (int c = 0; c < 4; c++) {
        if (c < 3) loadA_regs(pa, A, m0, (c + 1) * 32, lr, lc);
        compute_chunk(acc2, As, Wsm, c * 32, tx, ty);
        __syncthreads();
        if (c < 3) { storeA_smem(As, pa, lr, lc); __syncthreads(); }
    }

#pragma unroll
    for (int i = 0; i < 8; i++) {
        int m = m0 + ty * 8 + i;
        if (m < NN) {
#pragma unroll
            for (int jp = 0; jp < 4; jp += 2) {
                float2 p0 = *(float2*)&acc2[i][jp];
                float2 p1 = *(float2*)&acc2[i][jp + 1];
                int ccol = tx * 8 + jp * 2;
                float4 o;
                o.x = p0.x + __ldg(&bias[ccol + 0]);
                o.y = p0.y + __ldg(&bias[ccol + 1]);
                o.z = p1.x + __ldg(&bias[ccol + 2]);
                o.w = p1.y + __ldg(&bias[ccol + 3]);
                *(float4*)&C[(size_t)m * HID + ccol] = o;
            }
        }
    }
}

// ---------------- layer-0 node projection (K=12) ----------------
__global__ void node_proj12(const float* __restrict__ x,
                            const float* __restrict__ Wl, const float* __restrict__ bl,
                            const float* __restrict__ Wr, const float* __restrict__ br) {
    int idx = blockIdx.x * blockDim.x + threadIdx.x;
    int n = idx >> 7, j = idx & 127;
    float a = __ldg(&bl[j]);
    float b = __ldg(&br[j]);
#pragma unroll
    for (int k = 0; k < 12; k++) {
        float xv = __ldg(&x[n * 12 + k]);
        a = fmaf(xv, __ldg(&Wl[k * HID + j]), a);
        b = fmaf(xv, __ldg(&Wr[k * HID + j]), b);
    }
    g_xl[idx] = a;
    g_xr[idx] = b;
}

// ------- fused per-node: softmax + aggregate + bias + LN + SiLU (+res) ----------
template <bool RES, bool LAST>
__global__ void node_fused_kernel(const float* __restrict__ gat_bias,
                                  const float* __restrict__ lng,
                                  const float* __restrict__ lnb,
                                  float* __restrict__ dout) {
    int n = blockIdx.x * 4 + (threadIdx.x >> 5);
    int lane = threadIdx.x & 31;
    if (n >= NN) return;
    int s0 = g_rowptr[n];
    int s1 = g_rowptr[n + 1];

    float mx = -3.4e38f;
    for (int p = s0 * 4 + lane; p < s1 * 4; p += 32)
        mx = fmaxf(mx, g_score[p]);
    mx = fmaxf(mx, __shfl_xor_sync(0xffffffffu, mx, 4));
    mx = fmaxf(mx, __shfl_xor_sync(0xffffffffu, mx, 8));
    mx = fmaxf(mx, __shfl_xor_sync(0xffffffffu, mx, 16));

    float den = 0.f;
    for (int p = s0 * 4 + lane; p < s1 * 4; p += 32)
        den += __expf(g_score[p] - mx);
    den += __shfl_xor_sync(0xffffffffu, den, 4);
    den += __shfl_xor_sync(0xffffffffu, den, 8);
    den += __shfl_xor_sync(0xffffffffu, den, 16);
    float inv = __fdividef(1.f, den + 1e-16f);

    float acc0 = 0.f, acc1 = 0.f, acc2 = 0.f, acc3 = 0.f;
    for (int i = s0; i < s1; i++) {
        int src = g_srcs[i];
        float a = 0.f;
        if (lane < 4) a = __expf(g_score[(size_t)i * 4 + lane] - mx) * inv;
        float al0 = __shfl_sync(0xffffffffu, a, 0);
        float al1 = __shfl_sync(0xffffffffu, a, 1);
        float al2 = __shfl_sync(0xffffffffu, a, 2);
        float al3 = __shfl_sync(0xffffffffu, a, 3);
        const float* xl = &g_xl[(size_t)src * HID];
        acc0 = fmaf(xl[0 * DH + lane], al0, acc0);
        acc1 = fmaf(xl[1 * DH + lane], al1, acc1);
        acc2 = fmaf(xl[2 * DH + lane], al2, acc2);
        acc3 = fmaf(xl[3 * DH + lane], al3, acc3);
    }

    float v0 = acc0 + __ldg(&gat_bias[0 * DH + lane]);
    float v1 = acc1 + __ldg(&gat_bias[1 * DH + lane]);
    float v2 = acc2 + __ldg(&gat_bias[2 * DH + lane]);
    float v3 = acc3 + __ldg(&gat_bias[3 * DH + lane]);

    float sm = v0 + v1 + v2 + v3;
#pragma unroll
    for (int off = 16; off; off >>= 1) sm += __shfl_xor_sync(0xffffffffu, sm, off);
    float mean = sm * (1.f / 128.f);
    float d0 = v0 - mean, d1 = v1 - mean, d2 = v2 - mean, d3 = v3 - mean;
    float sq = d0 * d0 + d1 * d1 + d2 * d2 + d3 * d3;
#pragma unroll
    for (int off = 16; off; off >>= 1) sq += __shfl_xor_sync(0xffffffffu, sq, off);
    float rstd = rsqrtf(sq * (1.f / 128.f) + 1e-5f);

#pragma unroll
    for (int h = 0; h < 4; h++) {
        int j = h * DH + lane;
        float d = (h == 0 ? d0 : h == 1 ? d1 : h == 2 ? d2 : d3);
        float t = fmaf(d * rstd, __ldg(&lng[j]), __ldg(&lnb[j]));
        float sil = fast_silu(t);
        float o = RES ? (g_h[n * HID + j] + sil) : sil;
        if (LAST) dout[n * HID + j] = o;
        else      g_h[n * HID + j] = o;
    }
}

// ---------------- launch ----------------
extern "C" void kernel_launch(void* const* d_in, const int* in_sizes, int n_in,
                              void* d_out, int out_size) {
    const float* x     = (const float*)d_in[0];
    const int*   ei    = (const int*)  d_in[1];
    const float* eattr = (const float*)d_in[2];
    const float* epw   = (const float*)d_in[3];
    const float* epb   = (const float*)d_in[4];
    const float* l0Wl  = (const float*)d_in[5];
    const float* l0bl  = (const float*)d_in[6];
    const float* l0Wr  = (const float*)d_in[7];
    const float* l0br  = (const float*)d_in[8];
    const float* l0We  = (const float*)d_in[9];
    const float* l0att = (const float*)d_in[10];
    const float* l0bias= (const float*)d_in[11];
    const float* Wl    = (const float*)d_in[12];
    const float* bl    = (const float*)d_in[13];
    const float* Wr    = (const float*)d_in[14];
    const float* br    = (const float*)d_in[15];
    const float* We    = (const float*)d_in[16];
    const float* att   = (const float*)d_in[17];
    const float* bias  = (const float*)d_in[18];
    const float* lng   = (const float*)d_in[19];
    const float* lnb   = (const float*)d_in[20];
    float* out = (float*)d_out;

    const int NODE_SMEM = (WS_FLOATS + AS_FLOATS) * 4;
    static bool attr_set = false;
    if (!attr_set) {
        cudaFuncSetAttribute(gemm_edge_score_mma,
                             cudaFuncAttributeMaxDynamicSharedMemorySize, ESM_BYTES);
        cudaFuncSetAttribute(gemm_node,
                             cudaFuncAttributeMaxDynamicSharedMemorySize, NODE_SMEM);
        attr_set = true;
    }

    // independent prep
    eproj_kernel<<<(EE * 32) / 256, 256>>>(eattr, epw, epb);
    node_proj12<<<(NN * HID) / 256, 256>>>(x, l0Wl, l0bl, l0Wr, l0br);
    wprep_kernel<<<32, 256>>>(l0We);

    // CSR build (must precede the first edge GEMM)
    zero_kernel<<<(NN + 255) / 256, 256>>>();
    hist_kernel<<<(EE + 255) / 256, 256>>>(ei);
    deg_block_sum<<<NBLK, 1024>>>();
    bsum_scan<<<1, 128>>>();
    rowptr_kernel<<<NBLK, 1024>>>();
    scatter_kernel<<<(EE + 255) / 256, 256>>>(ei);

    // layer 0
    gemm_edge_score_mma<<<EE / 128, 256, ESM_BYTES>>>(l0att);
    node_fused_kernel<false, false><<<NN / 4, 128>>>(l0bias, lng, lnb, nullptr);

    // layers 1..3 (residual)
    for (int i = 0; i < 3; i++) {
        dim3 ng((NN + 127) / 128, 2);
        gemm_node<<<ng, 256, NODE_SMEM>>>(Wl + i * HID * HID, bl + i * HID,
                                          Wr + i * HID * HID, br + i * HID);
        wprep_kernel<<<32, 256>>>(We + i * HID * HID);
        gemm_edge_score_mma<<<EE / 128, 256, ESM_BYTES>>>(att + i * HID);
        if (i < 2)
            node_fused_kernel<true, false><<<NN / 4, 128>>>(
                bias + i * HID, lng + (i + 1) * HID, lnb + (i + 1) * HID, nullptr);
        else
            node_fused_kernel<true, true><<<NN / 4, 128>>>(
                bias + i * HID, lng + (i + 1) * HID, lnb + (i + 1) * HID, out);
    }
}

// round 12
// speedup vs baseline: 2.0356x; 1.0394x over previous
#include <cuda_runtime.h>
#include <cuda_bf16.h>
#include <math.h>
#include <stdint.h>

#define NN 100000
#define EE 800000
#define HID 128
#define NH 4
#define DH 32
#define NBLK ((NN + 1023) / 1024)   // 98
#define EPAD 68
#define TW (128 * EPAD)             // words per 128-row image (8704)
#define TB (TW * 4)                 // bytes per image (34816)
#define ESM_BYTES (4 * TB)          // Whi | Wlo | Ahi | Alo = 139264 B
#define XLPAD 132                   // xl prefetch row stride (floats)

// ---------------- scratch (static device globals; no allocation) ----------------
__device__ unsigned int g_Ahi[(size_t)EE * 64];   // edge feats bf16-hi pairs [e][kw]
__device__ unsigned int g_Alo[(size_t)EE * 64];
__device__ float g_xl[NN * HID];
__device__ float g_xr[NN * HID];
__device__ float g_h [NN * HID];
__device__ float g_score[EE * NH];                // CSR-position-indexed
__device__ unsigned int g_WhiE[8192], g_WloE[8192];
__device__ int g_deg[NN], g_cursor[NN], g_rowptr[NN + 1];
__device__ int g_eids[EE];
__device__ int2 g_sd[EE];                         // (src, dst) per CSR position
__device__ int g_bsum[NBLK], g_boff[NBLK];

// ---------------- helpers ----------------
__device__ __forceinline__ float fast_silu(float z) {
    return __fdividef(z, 1.0f + __expf(-z));
}
__device__ __forceinline__ unsigned int packbf2(float x, float y) {
    __nv_bfloat162 t = __floats2bfloat162_rn(x, y);
    return *(unsigned int*)&t;
}
__device__ __forceinline__ void bf_split(float x, float& hi, float& lo) {
    __nv_bfloat16 h = __float2bfloat16_rn(x);
    hi = __bfloat162float(h);
    lo = x - hi;
}
__device__ __forceinline__ void mma_bf16(float c[4],
                                         unsigned int a0, unsigned int a1,
                                         unsigned int a2, unsigned int a3,
                                         unsigned int b0, unsigned int b1) {
    asm volatile("mma.sync.aligned.m16n8k16.row.col.f32.bf16.bf16.f32 "
                 "{%0,%1,%2,%3}, {%4,%5,%6,%7}, {%8,%9}, {%0,%1,%2,%3};"
                 : "+f"(c[0]), "+f"(c[1]), "+f"(c[2]), "+f"(c[3])
                 : "r"(a0), "r"(a1), "r"(a2), "r"(a3), "r"(b0), "r"(b1));
}
__device__ __forceinline__ void ldsm4(unsigned int r[4], uint32_t addr) {
    asm volatile("ldmatrix.sync.aligned.m8n8.x4.shared.b16 {%0,%1,%2,%3}, [%4];"
                 : "=r"(r[0]), "=r"(r[1]), "=r"(r[2]), "=r"(r[3]) : "r"(addr));
}
// packed fp32x2 (FFMA2) for the node GEMM
__device__ __forceinline__ unsigned long long pack2(float x, float y) {
    unsigned long long r;
    asm("mov.b64 %0, {%1, %2};" : "=l"(r) : "f"(x), "f"(y));
    return r;
}
__device__ __forceinline__ unsigned long long bcast2(float x) {
    unsigned long long r;
    asm("mov.b64 %0, {%1, %1};" : "=l"(r) : "f"(x));
    return r;
}
__device__ __forceinline__ void ffma2(unsigned long long& d,
                                      unsigned long long a, unsigned long long b) {
    asm("fma.rn.f32x2 %0, %1, %2, %0;" : "+l"(d) : "l"(a), "l"(b));
}
__device__ __forceinline__ uint32_t smem_u32(const void* p) {
    uint32_t a;
    asm("{ .reg .u64 t; cvta.to.shared.u64 t, %1; cvt.u32.u64 %0, t; }" : "=r"(a) : "l"(p));
    return a;
}
__device__ __forceinline__ void cp16(uint32_t d, const void* s) {
    size_t gs = __cvta_generic_to_global((void*)s);
    asm volatile("cp.async.cg.shared.global [%0], [%1], 16;"
                 :: "r"(d), "l"((unsigned long long)gs) : "memory");
}
__device__ __forceinline__ void cp_commit() {
    asm volatile("cp.async.commit_group;" ::: "memory");
}
template <int N>
__device__ __forceinline__ void cp_wait() {
    asm volatile("cp.async.wait_group %0;" :: "n"(N) : "memory");
}

// ---------------- edge feature projection: bf16 hi/lo pair images ----------------
__global__ void eproj_kernel(const float* __restrict__ attr,
                             const float* __restrict__ W,
                             const float* __restrict__ b) {
    int idx = blockIdx.x * blockDim.x + threadIdx.x;   // E*32 threads
    int e = idx >> 5, c4 = (idx & 31) << 2;
    float a0 = __ldg(&attr[e * 3 + 0]);
    float a1 = __ldg(&attr[e * 3 + 1]);
    float a2 = __ldg(&attr[e * 3 + 2]);
    float v[4];
#pragma unroll
    for (int u = 0; u < 4; u++) {
        int j = c4 + u;
        float z = __ldg(&b[j]);
        z = fmaf(a0, __ldg(&W[j]),           z);
        z = fmaf(a1, __ldg(&W[HID + j]),     z);
        z = fmaf(a2, __ldg(&W[2 * HID + j]), z);
        v[u] = fast_silu(z);
    }
    float h0, l0, h1, l1, h2, l2, h3, l3;
    bf_split(v[0], h0, l0); bf_split(v[1], h1, l1);
    bf_split(v[2], h2, l2); bf_split(v[3], h3, l3);
    size_t base = (size_t)e * 64 + (c4 >> 1);
    *(uint2*)&g_Ahi[base] = make_uint2(packbf2(h0, h1), packbf2(h2, h3));
    *(uint2*)&g_Alo[base] = make_uint2(packbf2(l0, l1), packbf2(l2, l3));
}

// ---------------- CSR build (by dst) ----------------
__global__ void zero_kernel() {
    int i = blockIdx.x * blockDim.x + threadIdx.x;
    if (i < NN) { g_deg[i] = 0; g_cursor[i] = 0; }
}
__global__ void hist_kernel(const int* __restrict__ ei) {
    int e = blockIdx.x * blockDim.x + threadIdx.x;
    if (e < EE) atomicAdd(&g_deg[ei[EE + e]], 1);
}
__global__ void deg_block_sum() {
    __shared__ int sh[1024];
    int i = blockIdx.x * 1024 + threadIdx.x;
    sh[threadIdx.x] = (i < NN) ? g_deg[i] : 0;
    __syncthreads();
    for (int off = 512; off; off >>= 1) {
        if (threadIdx.x < off) sh[threadIdx.x] += sh[threadIdx.x + off];
        __syncthreads();
    }
    if (threadIdx.x == 0) g_bsum[blockIdx.x] = sh[0];
}
__global__ void bsum_scan() {
    __shared__ int sh[128];
    int t = threadIdx.x;
    int v = (t < NBLK) ? g_bsum[t] : 0;
    sh[t] = v;
    __syncthreads();
    for (int off = 1; off < 128; off <<= 1) {
        int u = (t >= off) ? sh[t - off] : 0;
        __syncthreads();
        sh[t] += u;
        __syncthreads();
    }
    if (t < NBLK) g_boff[t] = sh[t] - v;
}
__global__ void rowptr_kernel() {
    __shared__ int sh[1024];
    int i = blockIdx.x * 1024 + threadIdx.x;
    int v = (i < NN) ? g_deg[i] : 0;
    sh[threadIdx.x] = v;
    __syncthreads();
    for (int off = 1; off < 1024; off <<= 1) {
        int u = (threadIdx.x >= off) ? sh[threadIdx.x - off] : 0;
        __syncthreads();
        sh[threadIdx.x] += u;
        __syncthreads();
    }
    if (i < NN) g_rowptr[i + 1] = sh[threadIdx.x] + g_boff[blockIdx.x];
    if (i == 0) g_rowptr[0] = 0;
}
__global__ void scatter_kernel(const int* __restrict__ ei) {
    int e = blockIdx.x * blockDim.x + threadIdx.x;
    if (e < EE) {
        int src = ei[e];
        int d = ei[EE + e];
        int pos = g_rowptr[d] + atomicAdd(&g_cursor[d], 1);
        g_eids[pos] = e;
        g_sd[pos] = make_int2(src, d);
    }
}

// ---------------- W image prep (edge We) ----------------
__global__ void wprep_kernel(const float* __restrict__ W) {
    int idx = blockIdx.x * 256 + threadIdx.x;   // 8192
    int n = idx >> 6, kw = idx & 63;
    float w0 = __ldg(&W[(2 * kw) * HID + n]);
    float w1 = __ldg(&W[(2 * kw + 1) * HID + n]);
    float h0, l0, h1, l1;
    bf_split(w0, h0, l0);
    bf_split(w1, h1, l1);
    g_WhiE[idx] = packbf2(h0, h1);
    g_WloE[idx] = packbf2(l0, l1);
}

// ---- one bf16 mma pass over the tile via ldmatrix (8 K-steps) ----
__device__ __forceinline__ void pass_mma(float acc[2][8][4],
                                         uint32_t aBase, uint32_t bBase,
                                         int mb, int nb, int lane) {
    // per-lane ldmatrix address offsets (bytes)
    uint32_t aoff = (uint32_t)(((mb + (lane & 15)) * EPAD + ((lane >> 4) << 2)) * 4);
    uint32_t boff = (uint32_t)(((nb + (lane & 7) + ((lane >> 4) << 3)) * EPAD
                                + (((lane >> 3) & 1) << 2)) * 4);
    uint32_t a0a = aBase + aoff;
    uint32_t a1a = a0a + 16 * EPAD * 4;
    uint32_t bja = bBase + boff;
#pragma unroll
    for (int ks = 0; ks < 8; ks++) {
        unsigned int a0[4], a1[4];
        ldsm4(a0, a0a + ks * 32);
        ldsm4(a1, a1a + ks * 32);
        unsigned int b[4][4];
#pragma unroll
        for (int jj = 0; jj < 4; jj++)
            ldsm4(b[jj], bja + (uint32_t)(jj * 16 * EPAD * 4) + ks * 32);
#pragma unroll
        for (int jj = 0; jj < 4; jj++) {
            mma_bf16(acc[0][2 * jj + 0], a0[0], a0[1], a0[2], a0[3], b[jj][0], b[jj][1]);
            mma_bf16(acc[0][2 * jj + 1], a0[0], a0[1], a0[2], a0[3], b[jj][2], b[jj][3]);
            mma_bf16(acc[1][2 * jj + 0], a1[0], a1[1], a1[2], a1[3], b[jj][0], b[jj][1]);
            mma_bf16(acc[1][2 * jj + 1], a1[0], a1[1], a1[2], a1[3], b[jj][2], b[jj][3]);
        }
    }
}

// ---- prefetch 64 xl rows (CSR positions p0..p0+63) into a dead smem image ----
__device__ __forceinline__ void prefetch_xl(uint32_t dstbase, int p0, int tid) {
#pragma unroll
    for (int i = 0; i < 8; i++) {
        int idx = i * 256 + tid;              // 2048 chunks of 16B
        int row = idx >> 5;                   // 0..63
        int c = (idx & 31) << 2;              // float col
        int src = __ldg(&g_sd[p0 + row].x);
        cp16(dstbase + (uint32_t)(row * XLPAD + c) * 4,
             &g_xl[(size_t)src * HID + c]);
    }
    cp_commit();
}

// ================= edge GEMM + fused score (CSR tiles, ldmatrix) ================
__global__ __launch_bounds__(256, 1) void gemm_edge_score_mma(
        const float* __restrict__ att) {
    extern __shared__ __align__(16) unsigned int esm[];
    // layout: Whi[TW] | Wlo[TW] | Ahi[TW] | Alo[TW]
    uint32_t sb = smem_u32(esm);
    int tid = threadIdx.x;
    int m0 = blockIdx.x * 128;   // CSR positions m0..m0+127

    // stage A (hi/lo) via cp.async with eid indirection (dst-sorted order)
#pragma unroll
    for (int i = 0; i < 8; i++) {
        int idx = i * 256 + tid;              // 2048 chunks
        int row = idx >> 4, c = (idx & 15) << 2;
        int eid = __ldg(&g_eids[m0 + row]);
        uint32_t doff = (uint32_t)(row * EPAD + c) * 4;
        cp16(sb + 2 * TB + doff, &g_Ahi[(size_t)eid * 64 + c]);
        cp16(sb + 3 * TB + doff, &g_Alo[(size_t)eid * 64 + c]);
    }
    cp_commit();

    // stage W (regular uint4 loads; L2-resident)
#pragma unroll
    for (int i = 0; i < 8; i++) {
        int idx = i * 256 + tid;
        int n = idx >> 4, c = (idx & 15) << 2;
        uint4 vh = ((const uint4*)g_WhiE)[idx];
        uint4 vl = ((const uint4*)g_WloE)[idx];
        *(uint4*)&esm[n * EPAD + c] = vh;
        *(uint4*)&esm[TW + n * EPAD + c] = vl;
    }
    cp_wait<0>();
    __syncthreads();

    int wid = tid >> 5, lane = tid & 31, g = lane >> 2, q = lane & 3;
    int mb = (wid & 3) * 32;        // 4 row groups
    int nb = (wid >> 2) * 64;       // 2 col groups (2 heads each)

    float acc[2][8][4];
#pragma unroll
    for (int t = 0; t < 2; t++)
#pragma unroll
        for (int j = 0; j < 8; j++)
#pragma unroll
            for (int c = 0; c < 4; c++) acc[t][j][c] = 0.f;

    // pass 0: (Alo, Whi) — frees Alo
    pass_mma(acc, sb + 3 * TB, sb, mb, nb, lane);
    __syncthreads();
    prefetch_xl(sb + 3 * TB, m0, tid);          // xl rows 0..63 -> Alo space

    // pass 1: (Ahi, Wlo) — frees Wlo (cp.async overlaps)
    pass_mma(acc, sb + 2 * TB, sb + 1 * TB, mb, nb, lane);
    __syncthreads();
    prefetch_xl(sb + 1 * TB, m0 + 64, tid);     // xl rows 64..127 -> Wlo space

    // pass 2: (Ahi, Whi) (cp.async overlaps)
    pass_mma(acc, sb + 2 * TB, sb, mb, nb, lane);
    cp_wait<0>();
    __syncthreads();

    // fused epilogue: xl from smem, xr via L1 (dst-sorted reuse)
    const float* xlb0 = (const float*)(esm + 3 * TW);
    const float* xlb1 = (const float*)(esm + 1 * TW);
    float2 attv[8];
#pragma unroll
    for (int j = 0; j < 8; j++)
        attv[j] = *(const float2*)&att[nb + 8 * j + 2 * q];

#pragma unroll
    for (int t = 0; t < 2; t++) {
#pragma unroll
        for (int rr = 0; rr < 2; rr++) {
            int row = mb + 16 * t + 8 * rr + g;
            int pos = m0 + row;
            int2 sd = __ldg(&g_sd[pos]);
            const float* xlp = (row < 64) ? (xlb0 + row * XLPAD)
                                          : (xlb1 + (row - 64) * XLPAD);
            const float* xrp = &g_xr[(size_t)sd.y * HID];
            float p0 = 0.f, p1 = 0.f;
#pragma unroll
            for (int j = 0; j < 8; j++) {
                int cc = nb + 8 * j + 2 * q;
                float2 xl = *(const float2*)&xlp[cc];
                float2 xr = *(const float2*)&xrp[cc];
                float e0 = acc[t][j][rr * 2 + 0] + xl.x + xr.x;
                float e1 = acc[t][j][rr * 2 + 1] + xl.y + xr.y;
                e0 = (e0 > 0.f) ? e0 : 0.2f * e0;
                e1 = (e1 > 0.f) ? e1 : 0.2f * e1;
                float ps = fmaf(e0, attv[j].x, e1 * attv[j].y);
                if (j < 4) p0 += ps; else p1 += ps;
            }
            p0 += __shfl_xor_sync(0xffffffffu, p0, 1);
            p0 += __shfl_xor_sync(0xffffffffu, p0, 2);
            p1 += __shfl_xor_sync(0xffffffffu, p1, 1);
            p1 += __shfl_xor_sync(0xffffffffu, p1, 2);
            if (q == 0)
                *(float2*)&g_score[(size_t)pos * 4 + (nb >> 5)] =
                    make_float2(p0, p1);
        }
    }
}

// ================= SIMT node GEMM (proven FFMA2 path) ==================
#define WS_FLOATS (HID * HID)
#define AS_PAD 132
#define AS_FLOATS (32 * AS_PAD)

__device__ __forceinline__ void load_W_smem(float* Wsm, const float* __restrict__ W, int tid) {
    const float4* Wv = (const float4*)W;
    float4* Wd = (float4*)Wsm;
#pragma unroll
    for (int i = 0; i < WS_FLOATS / 4 / 256; i++)
        Wd[tid + 256 * i] = Wv[tid + 256 * i];
}
__device__ __forceinline__ void loadA_regs(float4 pa[4], const float* __restrict__ A,
                                           int m0, int k0, int lr, int lc) {
#pragma unroll
    for (int i = 0; i < 4; i++) {
        int m = m0 + lr + 32 * i;
        if (m < NN)
            pa[i] = *(const float4*)&A[(size_t)m * HID + k0 + lc];
        else
            pa[i] = make_float4(0.f, 0.f, 0.f, 0.f);
    }
}
__device__ __forceinline__ void storeA_smem(float* As, const float4 pa[4], int lr, int lc) {
#pragma unroll
    for (int i = 0; i < 4; i++) {
        As[(lc + 0) * AS_PAD + lr + 32 * i] = pa[i].x;
        As[(lc + 1) * AS_PAD + lr + 32 * i] = pa[i].y;
        As[(lc + 2) * AS_PAD + lr + 32 * i] = pa[i].z;
        As[(lc + 3) * AS_PAD + lr + 32 * i] = pa[i].w;
    }
}
__device__ __forceinline__ void compute_chunk(unsigned long long acc2[8][4],
                                              const float* As, const float* Wsm,
                                              int k0, int tx, int ty) {
#pragma unroll 8
    for (int kk = 0; kk < 32; kk++) {
        float4 a0 = *(const float4*)&As[kk * AS_PAD + ty * 8];
        float4 a1 = *(const float4*)&As[kk * AS_PAD + ty * 8 + 4];
        float4 b0 = *(const float4*)&Wsm[(k0 + kk) * HID + tx * 8];
        float4 b1 = *(const float4*)&Wsm[(k0 + kk) * HID + tx * 8 + 4];
        unsigned long long bp[4] = {pack2(b0.x, b0.y), pack2(b0.z, b0.w),
                                    pack2(b1.x, b1.y), pack2(b1.z, b1.w)};
        float a[8] = {a0.x, a0.y, a0.z, a0.w, a1.x, a1.y, a1.z, a1.w};
#pragma unroll
        for (int i = 0; i < 8; i++) {
            unsigned long long ap = bcast2(a[i]);
#pragma unroll
            for (int j = 0; j < 4; j++) ffma2(acc2[i][j], ap, bp[j]);
        }
    }
}

__global__ __launch_bounds__(256, 2) void gemm_node(const float* __restrict__ Wl,
                                                    const float* __restrict__ bl,
                                                    const float* __restrict__ Wr,
                                                    const float* __restrict__ br) {
    extern __shared__ __align__(16) float smem[];
    float* Wsm = smem;
    float* As = smem + WS_FLOATS;

    const float* W    = blockIdx.y ? Wr : Wl;
    const float* bias = blockIdx.y ? br : bl;
    float* C          = blockIdx.y ? g_xr : g_xl;
    const float* A = g_h;

    int tid = threadIdx.x;
    int tx = tid & 15, ty = tid >> 4;
    int lr = tid >> 3, lc = (tid & 7) << 2;
    int m0 = blockIdx.x * 128;

    load_W_smem(Wsm, W, tid);

    unsigned long long acc2[8][4];
#pragma unroll
    for (int i = 0; i < 8; i++)
#pragma unroll
        for (int j = 0; j < 4; j++) acc2[i][j] = 0ull;

    float4 pa[4];
    loadA_regs(pa, A, m0, 0, lr, lc);
    storeA_smem(As, pa, lr, lc);
    __syncthreads();

#pragma unroll
    for (int c = 0; c < 4; c++) {
        if (c < 3) loadA_regs(pa, A, m0, (c + 1) * 32, lr, lc);
        compute_chunk(acc2, As, Wsm, c * 32, tx, ty);
        __syncthreads();
        if (c < 3) { storeA_smem(As, pa, lr, lc); __syncthreads(); }
    }

#pragma unroll
    for (int i = 0; i < 8; i++) {
        int m = m0 + ty * 8 + i;
        if (m < NN) {
#pragma unroll
            for (int jp = 0; jp < 4; jp += 2) {
                float2 p0 = *(float2*)&acc2[i][jp];
                float2 p1 = *(float2*)&acc2[i][jp + 1];
                int ccol = tx * 8 + jp * 2;
                float4 o;
                o.x = p0.x + __ldg(&bias[ccol + 0]);
                o.y = p0.y + __ldg(&bias[ccol + 1]);
                o.z = p1.x + __ldg(&bias[ccol + 2]);
                o.w = p1.y + __ldg(&bias[ccol + 3]);
                *(float4*)&C[(size_t)m * HID + ccol] = o;
            }
        }
    }
}

// ---------------- layer-0 node projection (K=12) ----------------
__global__ void node_proj12(const float* __restrict__ x,
                            const float* __restrict__ Wl, const float* __restrict__ bl,
                            const float* __restrict__ Wr, const float* __restrict__ br) {
    int idx = blockIdx.x * blockDim.x + threadIdx.x;
    int n = idx >> 7, j = idx & 127;
    float a = __ldg(&bl[j]);
    float b = __ldg(&br[j]);
#pragma unroll
    for (int k = 0; k < 12; k++) {
        float xv = __ldg(&x[n * 12 + k]);
        a = fmaf(xv, __ldg(&Wl[k * HID + j]), a);
        b = fmaf(xv, __ldg(&Wr[k * HID + j]), b);
    }
    g_xl[idx] = a;
    g_xr[idx] = b;
}

// ------- fused per-node: softmax + aggregate + bias + LN + SiLU (+res) ----------
template <bool RES, bool LAST>
__global__ void node_fused_kernel(const float* __restrict__ gat_bias,
                                  const float* __restrict__ lng,
                                  const float* __restrict__ lnb,
                                  float* __restrict__ dout) {
    int n = blockIdx.x * 4 + (threadIdx.x >> 5);
    int lane = threadIdx.x & 31;
    if (n >= NN) return;
    int s0 = g_rowptr[n];
    int s1 = g_rowptr[n + 1];

    float mx = -3.4e38f;
    for (int p = s0 * 4 + lane; p < s1 * 4; p += 32)
        mx = fmaxf(mx, g_score[p]);
    mx = fmaxf(mx, __shfl_xor_sync(0xffffffffu, mx, 4));
    mx = fmaxf(mx, __shfl_xor_sync(0xffffffffu, mx, 8));
    mx = fmaxf(mx, __shfl_xor_sync(0xffffffffu, mx, 16));

    float den = 0.f;
    for (int p = s0 * 4 + lane; p < s1 * 4; p += 32)
        den += __expf(g_score[p] - mx);
    den += __shfl_xor_sync(0xffffffffu, den, 4);
    den += __shfl_xor_sync(0xffffffffu, den, 8);
    den += __shfl_xor_sync(0xffffffffu, den, 16);
    float inv = __fdividef(1.f, den + 1e-16f);

    float acc0 = 0.f, acc1 = 0.f, acc2 = 0.f, acc3 = 0.f;
    for (int i = s0; i < s1; i++) {
        int src = g_sd[i].x;
        float a = 0.f;
        if (lane < 4) a = __expf(g_score[(size_t)i * 4 + lane] - mx) * inv;
        float al0 = __shfl_sync(0xffffffffu, a, 0);
        float al1 = __shfl_sync(0xffffffffu, a, 1);
        float al2 = __shfl_sync(0xffffffffu, a, 2);
        float al3 = __shfl_sync(0xffffffffu, a, 3);
        const float* xl = &g_xl[(size_t)src * HID];
        acc0 = fmaf(xl[0 * DH + lane], al0, acc0);
        acc1 = fmaf(xl[1 * DH + lane], al1, acc1);
        acc2 = fmaf(xl[2 * DH + lane], al2, acc2);
        acc3 = fmaf(xl[3 * DH + lane], al3, acc3);
    }

    float v0 = acc0 + __ldg(&gat_bias[0 * DH + lane]);
    float v1 = acc1 + __ldg(&gat_bias[1 * DH + lane]);
    float v2 = acc2 + __ldg(&gat_bias[2 * DH + lane]);
    float v3 = acc3 + __ldg(&gat_bias[3 * DH + lane]);

    float sm = v0 + v1 + v2 + v3;
#pragma unroll
    for (int off = 16; off; off >>= 1) sm += __shfl_xor_sync(0xffffffffu, sm, off);
    float mean = sm * (1.f / 128.f);
    float d0 = v0 - mean, d1 = v1 - mean, d2 = v2 - mean, d3 = v3 - mean;
    float sq = d0 * d0 + d1 * d1 + d2 * d2 + d3 * d3;
#pragma unroll
    for (int off = 16; off; off >>= 1) sq += __shfl_xor_sync(0xffffffffu, sq, off);
    float rstd = rsqrtf(sq * (1.f / 128.f) + 1e-5f);

#pragma unroll
    for (int h = 0; h < 4; h++) {
        int j = h * DH + lane;
        float d = (h == 0 ? d0 : h == 1 ? d1 : h == 2 ? d2 : d3);
        float t = fmaf(d * rstd, __ldg(&lng[j]), __ldg(&lnb[j]));
        float sil = fast_silu(t);
        float o = RES ? (g_h[n * HID + j] + sil) : sil;
        if (LAST) dout[n * HID + j] = o;
        else      g_h[n * HID + j] = o;
    }
}

// ---------------- launch ----------------
extern "C" void kernel_launch(void* const* d_in, const int* in_sizes, int n_in,
                              void* d_out, int out_size) {
    const float* x     = (const float*)d_in[0];
    const int*   ei    = (const int*)  d_in[1];
    const float* eattr = (const float*)d_in[2];
    const float* epw   = (const float*)d_in[3];
    const float* epb   = (const float*)d_in[4];
    const float* l0Wl  = (const float*)d_in[5];
    const float* l0bl  = (const float*)d_in[6];
    const float* l0Wr  = (const float*)d_in[7];
    const float* l0br  = (const float*)d_in[8];
    const float* l0We  = (const float*)d_in[9];
    const float* l0att = (const float*)d_in[10];
    const float* l0bias= (const float*)d_in[11];
    const float* Wl    = (const float*)d_in[12];
    const float* bl    = (const float*)d_in[13];
    const float* Wr    = (const float*)d_in[14];
    const float* br    = (const float*)d_in[15];
    const float* We    = (const float*)d_in[16];
    const float* att   = (const float*)d_in[17];
    const float* bias  = (const float*)d_in[18];
    const float* lng   = (const float*)d_in[19];
    const float* lnb   = (const float*)d_in[20];
    float* out = (float*)d_out;

    const int NODE_SMEM = (WS_FLOATS + AS_FLOATS) * 4;
    static bool attr_set = false;
    if (!attr_set) {
        cudaFuncSetAttribute(gemm_edge_score_mma,
                             cudaFuncAttributeMaxDynamicSharedMemorySize, ESM_BYTES);
        cudaFuncSetAttribute(gemm_node,
                             cudaFuncAttributeMaxDynamicSharedMemorySize, NODE_SMEM);
        attr_set = true;
    }

    // independent prep
    eproj_kernel<<<(EE * 32) / 256, 256>>>(eattr, epw, epb);
    node_proj12<<<(NN * HID) / 256, 256>>>(x, l0Wl, l0bl, l0Wr, l0br);
    wprep_kernel<<<32, 256>>>(l0We);

    // CSR build (must precede the first edge GEMM)
    zero_kernel<<<(NN + 255) / 256, 256>>>();
    hist_kernel<<<(EE + 255) / 256, 256>>>(ei);
    deg_block_sum<<<NBLK, 1024>>>();
    bsum_scan<<<1, 128>>>();
    rowptr_kernel<<<NBLK, 1024>>>();
    scatter_kernel<<<(EE + 255) / 256, 256>>>(ei);

    // layer 0
    gemm_edge_score_mma<<<EE / 128, 256, ESM_BYTES>>>(l0att);
    node_fused_kernel<false, false><<<NN / 4, 128>>>(l0bias, lng, lnb, nullptr);

    // layers 1..3 (residual)
    for (int i = 0; i < 3; i++) {
        dim3 ng((NN + 127) / 128, 2);
        gemm_node<<<ng, 256, NODE_SMEM>>>(Wl + i * HID * HID, bl + i * HID,
                                          Wr + i * HID * HID, br + i * HID);
        wprep_kernel<<<32, 256>>>(We + i * HID * HID);
        gemm_edge_score_mma<<<EE / 128, 256, ESM_BYTES>>>(att + i * HID);
        if (i < 2)
            node_fused_kernel<true, false><<<NN / 4, 128>>>(
                bias + i * HID, lng + (i + 1) * HID, lnb + (i + 1) * HID, nullptr);
        else
            node_fused_kernel<true, true><<<NN / 4, 128>>>(
                bias + i * HID, lng + (i + 1) * HID, lnb + (i + 1) * HID, out);
    }
}

// round 13
// speedup vs baseline: 2.2152x; 1.0882x over previous
#include <cuda_runtime.h>
#include <cuda_bf16.h>
#include <math.h>
#include <stdint.h>

#define NN 100000
#define EE 800000
#define HID 128
#define NH 4
#define DH 32
#define NBLK ((NN + 1023) / 1024)   // 98
#define NPAD 100096
#define NTILES ((NN + 127) / 128)   // 782
#define EPAD 68
#define TW (128 * EPAD)             // words per 128-row image (8704)
#define TB (TW * 4)                 // bytes per image (34816)
#define ESM_BYTES (4 * TB)          // Whi | Wlo | Ahi | Alo = 139264 B
#define XLPAD 132                   // xl prefetch row stride (floats)

// ---------------- scratch (static device globals; no allocation) ----------------
__device__ unsigned int g_Ahi[(size_t)EE * 64];   // edge feats bf16-hi pairs (CSR order)
__device__ unsigned int g_Alo[(size_t)EE * 64];
__device__ unsigned int g_hhi[(size_t)NPAD * 64]; // hidden bf16 pair images
__device__ unsigned int g_hlo[(size_t)NPAD * 64];
__device__ float g_xl[NN * HID];
__device__ float g_xr[NN * HID];
__device__ float g_h [NN * HID];
__device__ float g_score[EE * NH];                // CSR-position-indexed
__device__ unsigned int g_WhiE[8192], g_WloE[8192];
__device__ unsigned int g_WhiL[8192], g_WloL[8192];
__device__ unsigned int g_WhiR[8192], g_WloR[8192];
__device__ int g_deg[NN], g_cursor[NN], g_rowptr[NN + 1];
__device__ int g_pos[EE];                         // edge id -> CSR position
__device__ int2 g_sd[EE];                         // (src, dst) per CSR position
__device__ int g_bsum[NBLK], g_boff[NBLK];

// ---------------- helpers ----------------
__device__ __forceinline__ float fast_silu(float z) {
    return __fdividef(z, 1.0f + __expf(-z));
}
__device__ __forceinline__ unsigned int packbf2(float x, float y) {
    __nv_bfloat162 t = __floats2bfloat162_rn(x, y);
    return *(unsigned int*)&t;
}
__device__ __forceinline__ void bf_split(float x, float& hi, float& lo) {
    __nv_bfloat16 h = __float2bfloat16_rn(x);
    hi = __bfloat162float(h);
    lo = x - hi;
}
__device__ __forceinline__ void mma_bf16(float c[4],
                                         unsigned int a0, unsigned int a1,
                                         unsigned int a2, unsigned int a3,
                                         unsigned int b0, unsigned int b1) {
    asm volatile("mma.sync.aligned.m16n8k16.row.col.f32.bf16.bf16.f32 "
                 "{%0,%1,%2,%3}, {%4,%5,%6,%7}, {%8,%9}, {%0,%1,%2,%3};"
                 : "+f"(c[0]), "+f"(c[1]), "+f"(c[2]), "+f"(c[3])
                 : "r"(a0), "r"(a1), "r"(a2), "r"(a3), "r"(b0), "r"(b1));
}
__device__ __forceinline__ void ldsm4(unsigned int r[4], uint32_t addr) {
    asm volatile("ldmatrix.sync.aligned.m8n8.x4.shared.b16 {%0,%1,%2,%3}, [%4];"
                 : "=r"(r[0]), "=r"(r[1]), "=r"(r[2]), "=r"(r[3]) : "r"(addr));
}
__device__ __forceinline__ uint32_t smem_u32(const void* p) {
    uint32_t a;
    asm("{ .reg .u64 t; cvta.to.shared.u64 t, %1; cvt.u32.u64 %0, t; }" : "=r"(a) : "l"(p));
    return a;
}
__device__ __forceinline__ void cp16(uint32_t d, const void* s) {
    size_t gs = __cvta_generic_to_global((void*)s);
    asm volatile("cp.async.cg.shared.global [%0], [%1], 16;"
                 :: "r"(d), "l"((unsigned long long)gs) : "memory");
}
__device__ __forceinline__ void cp_commit() {
    asm volatile("cp.async.commit_group;" ::: "memory");
}
template <int N>
__device__ __forceinline__ void cp_wait() {
    asm volatile("cp.async.wait_group %0;" :: "n"(N) : "memory");
}

// ---------------- CSR build (by dst) ----------------
__global__ void zero_kernel() {
    int i = blockIdx.x * blockDim.x + threadIdx.x;
    if (i < NN) { g_deg[i] = 0; g_cursor[i] = 0; }
    if (i < (NPAD - NN) * 64) {   // zero pad rows of h images
        g_hhi[(size_t)NN * 64 + i] = 0;
        g_hlo[(size_t)NN * 64 + i] = 0;
    }
}
__global__ void hist_kernel(const int* __restrict__ ei) {
    int e = blockIdx.x * blockDim.x + threadIdx.x;
    if (e < EE) atomicAdd(&g_deg[ei[EE + e]], 1);
}
__global__ void deg_block_sum() {
    __shared__ int sh[1024];
    int i = blockIdx.x * 1024 + threadIdx.x;
    sh[threadIdx.x] = (i < NN) ? g_deg[i] : 0;
    __syncthreads();
    for (int off = 512; off; off >>= 1) {
        if (threadIdx.x < off) sh[threadIdx.x] += sh[threadIdx.x + off];
        __syncthreads();
    }
    if (threadIdx.x == 0) g_bsum[blockIdx.x] = sh[0];
}
__global__ void bsum_scan() {
    __shared__ int sh[128];
    int t = threadIdx.x;
    int v = (t < NBLK) ? g_bsum[t] : 0;
    sh[t] = v;
    __syncthreads();
    for (int off = 1; off < 128; off <<= 1) {
        int u = (t >= off) ? sh[t - off] : 0;
        __syncthreads();
        sh[t] += u;
        __syncthreads();
    }
    if (t < NBLK) g_boff[t] = sh[t] - v;
}
__global__ void rowptr_kernel() {
    __shared__ int sh[1024];
    int i = blockIdx.x * 1024 + threadIdx.x;
    int v = (i < NN) ? g_deg[i] : 0;
    sh[threadIdx.x] = v;
    __syncthreads();
    for (int off = 1; off < 1024; off <<= 1) {
        int u = (threadIdx.x >= off) ? sh[threadIdx.x - off] : 0;
        __syncthreads();
        sh[threadIdx.x] += u;
        __syncthreads();
    }
    if (i < NN) g_rowptr[i + 1] = sh[threadIdx.x] + g_boff[blockIdx.x];
    if (i == 0) g_rowptr[0] = 0;
}
__global__ void scatter_kernel(const int* __restrict__ ei) {
    int e = blockIdx.x * blockDim.x + threadIdx.x;
    if (e < EE) {
        int src = ei[e];
        int d = ei[EE + e];
        int pos = g_rowptr[d] + atomicAdd(&g_cursor[d], 1);
        g_pos[e] = pos;
        g_sd[pos] = make_int2(src, d);
    }
}

// -------- edge feature projection: bf16 hi/lo images at CSR positions ----------
__global__ void eproj_kernel(const float* __restrict__ attr,
                             const float* __restrict__ W,
                             const float* __restrict__ b) {
    int idx = blockIdx.x * blockDim.x + threadIdx.x;   // E*32 threads
    int e = idx >> 5, c4 = (idx & 31) << 2;
    float a0 = __ldg(&attr[e * 3 + 0]);
    float a1 = __ldg(&attr[e * 3 + 1]);
    float a2 = __ldg(&attr[e * 3 + 2]);
    float v[4];
#pragma unroll
    for (int u = 0; u < 4; u++) {
        int j = c4 + u;
        float z = __ldg(&b[j]);
        z = fmaf(a0, __ldg(&W[j]),           z);
        z = fmaf(a1, __ldg(&W[HID + j]),     z);
        z = fmaf(a2, __ldg(&W[2 * HID + j]), z);
        v[u] = fast_silu(z);
    }
    float h0, l0, h1, l1, h2, l2, h3, l3;
    bf_split(v[0], h0, l0); bf_split(v[1], h1, l1);
    bf_split(v[2], h2, l2); bf_split(v[3], h3, l3);
    int pos = __ldg(&g_pos[e]);
    size_t base = (size_t)pos * 64 + (c4 >> 1);
    *(uint2*)&g_Ahi[base] = make_uint2(packbf2(h0, h1), packbf2(h2, h3));
    *(uint2*)&g_Alo[base] = make_uint2(packbf2(l0, l1), packbf2(l2, l3));
}

// ---------------- W image prep: 0 -> We, 1 -> Wl, 2 -> Wr ----------------
__global__ void wprep_kernel(const float* __restrict__ W, int which) {
    int idx = blockIdx.x * 256 + threadIdx.x;   // 8192
    int n = idx >> 6, kw = idx & 63;
    float w0 = __ldg(&W[(2 * kw) * HID + n]);
    float w1 = __ldg(&W[(2 * kw + 1) * HID + n]);
    float h0, l0, h1, l1;
    bf_split(w0, h0, l0);
    bf_split(w1, h1, l1);
    unsigned int* hi = (which == 0) ? g_WhiE : (which == 1) ? g_WhiL : g_WhiR;
    unsigned int* lo = (which == 0) ? g_WloE : (which == 1) ? g_WloL : g_WloR;
    hi[idx] = packbf2(h0, h1);
    lo[idx] = packbf2(l0, l1);
}

// ---- one bf16 mma pass over the tile via ldmatrix (8 K-steps) ----
__device__ __forceinline__ void pass_mma(float acc[2][8][4],
                                         uint32_t aBase, uint32_t bBase,
                                         int mb, int nb, int lane) {
    uint32_t aoff = (uint32_t)(((mb + (lane & 15)) * EPAD + ((lane >> 4) << 2)) * 4);
    uint32_t boff = (uint32_t)(((nb + (lane & 7) + ((lane >> 4) << 3)) * EPAD
                                + (((lane >> 3) & 1) << 2)) * 4);
    uint32_t a0a = aBase + aoff;
    uint32_t a1a = a0a + 16 * EPAD * 4;
    uint32_t bja = bBase + boff;
#pragma unroll
    for (int ks = 0; ks < 8; ks++) {
        unsigned int a0[4], a1[4];
        ldsm4(a0, a0a + ks * 32);
        ldsm4(a1, a1a + ks * 32);
        unsigned int b[4][4];
#pragma unroll
        for (int jj = 0; jj < 4; jj++)
            ldsm4(b[jj], bja + (uint32_t)(jj * 16 * EPAD * 4) + ks * 32);
#pragma unroll
        for (int jj = 0; jj < 4; jj++) {
            mma_bf16(acc[0][2 * jj + 0], a0[0], a0[1], a0[2], a0[3], b[jj][0], b[jj][1]);
            mma_bf16(acc[0][2 * jj + 1], a0[0], a0[1], a0[2], a0[3], b[jj][2], b[jj][3]);
            mma_bf16(acc[1][2 * jj + 0], a1[0], a1[1], a1[2], a1[3], b[jj][0], b[jj][1]);
            mma_bf16(acc[1][2 * jj + 1], a1[0], a1[1], a1[2], a1[3], b[jj][2], b[jj][3]);
        }
    }
}

// ---- staging helpers ----
__device__ __forceinline__ void stage_A_seq(uint32_t sb, const unsigned int* ghi,
                                            const unsigned int* glo, int m0, int tid) {
#pragma unroll
    for (int i = 0; i < 8; i++) {
        int idx = i * 256 + tid;
        int row = idx >> 4, c = (idx & 15) << 2;
        uint32_t doff = (uint32_t)(row * EPAD + c) * 4;
        cp16(sb + 2 * TB + doff, &ghi[(size_t)(m0 + row) * 64 + c]);
        cp16(sb + 3 * TB + doff, &glo[(size_t)(m0 + row) * 64 + c]);
    }
    cp_commit();
}
__device__ __forceinline__ void stage_W(unsigned int* esm, const unsigned int* gWhi,
                                        const unsigned int* gWlo, int tid) {
#pragma unroll
    for (int i = 0; i < 8; i++) {
        int idx = i * 256 + tid;
        int n = idx >> 4, c = (idx & 15) << 2;
        uint4 vh = ((const uint4*)gWhi)[idx];
        uint4 vl = ((const uint4*)gWlo)[idx];
        *(uint4*)&esm[n * EPAD + c] = vh;
        *(uint4*)&esm[TW + n * EPAD + c] = vl;
    }
}

// ---- prefetch 64 xl rows (CSR positions p0..p0+63) into a dead smem image ----
__device__ __forceinline__ void prefetch_xl(uint32_t dstbase, int p0, int tid) {
#pragma unroll
    for (int i = 0; i < 8; i++) {
        int idx = i * 256 + tid;
        int row = idx >> 5;
        int c = (idx & 31) << 2;
        int src = __ldg(&g_sd[p0 + row].x);
        cp16(dstbase + (uint32_t)(row * XLPAD + c) * 4,
             &g_xl[(size_t)src * HID + c]);
    }
    cp_commit();
}

// ================= edge GEMM + fused score (CSR tiles, ldmatrix) ================
__global__ __launch_bounds__(256, 1) void gemm_edge_score_mma(
        const float* __restrict__ att) {
    extern __shared__ __align__(16) unsigned int esm[];
    uint32_t sb = smem_u32(esm);
    int tid = threadIdx.x;
    int m0 = blockIdx.x * 128;

    stage_A_seq(sb, g_Ahi, g_Alo, m0, tid);
    stage_W(esm, g_WhiE, g_WloE, tid);
    cp_wait<0>();
    __syncthreads();

    int wid = tid >> 5, lane = tid & 31, g = lane >> 2, q = lane & 3;
    int mb = (wid & 3) * 32;
    int nb = (wid >> 2) * 64;

    float acc[2][8][4];
#pragma unroll
    for (int t = 0; t < 2; t++)
#pragma unroll
        for (int j = 0; j < 8; j++)
#pragma unroll
            for (int c = 0; c < 4; c++) acc[t][j][c] = 0.f;

    // pass 0: (Alo, Whi) — frees Alo
    pass_mma(acc, sb + 3 * TB, sb, mb, nb, lane);
    __syncthreads();
    prefetch_xl(sb + 3 * TB, m0, tid);

    // pass 1: (Ahi, Wlo) — frees Wlo
    pass_mma(acc, sb + 2 * TB, sb + 1 * TB, mb, nb, lane);
    __syncthreads();
    prefetch_xl(sb + 1 * TB, m0 + 64, tid);

    // pass 2: (Ahi, Whi)
    pass_mma(acc, sb + 2 * TB, sb, mb, nb, lane);
    cp_wait<0>();
    __syncthreads();

    const float* xlb0 = (const float*)(esm + 3 * TW);
    const float* xlb1 = (const float*)(esm + 1 * TW);
    float2 attv[8];
#pragma unroll
    for (int j = 0; j < 8; j++)
        attv[j] = *(const float2*)&att[nb + 8 * j + 2 * q];

#pragma unroll
    for (int t = 0; t < 2; t++) {
#pragma unroll
        for (int rr = 0; rr < 2; rr++) {
            int row = mb + 16 * t + 8 * rr + g;
            int pos = m0 + row;
            int2 sd = __ldg(&g_sd[pos]);
            const float* xlp = (row < 64) ? (xlb0 + row * XLPAD)
                                          : (xlb1 + (row - 64) * XLPAD);
            const float* xrp = &g_xr[(size_t)sd.y * HID];
            float p0 = 0.f, p1 = 0.f;
#pragma unroll
            for (int j = 0; j < 8; j++) {
                int cc = nb + 8 * j + 2 * q;
                float2 xl = *(const float2*)&xlp[cc];
                float2 xr = *(const float2*)&xrp[cc];
                float e0 = acc[t][j][rr * 2 + 0] + xl.x + xr.x;
                float e1 = acc[t][j][rr * 2 + 1] + xl.y + xr.y;
                e0 = (e0 > 0.f) ? e0 : 0.2f * e0;
                e1 = (e1 > 0.f) ? e1 : 0.2f * e1;
                float ps = fmaf(e0, attv[j].x, e1 * attv[j].y);
                if (j < 4) p0 += ps; else p1 += ps;
            }
            p0 += __shfl_xor_sync(0xffffffffu, p0, 1);
            p0 += __shfl_xor_sync(0xffffffffu, p0, 2);
            p1 += __shfl_xor_sync(0xffffffffu, p1, 1);
            p1 += __shfl_xor_sync(0xffffffffu, p1, 2);
            if (q == 0)
                *(float2*)&g_score[(size_t)pos * 4 + (nb >> 5)] =
                    make_float2(p0, p1);
        }
    }
}

// ============ node GEMM via same mma machinery (xl / xr by blockIdx.y) ==========
__global__ __launch_bounds__(256, 1) void gemm_node_mma(
        const float* __restrict__ bl, const float* __restrict__ br) {
    extern __shared__ __align__(16) unsigned int esm[];
    uint32_t sb = smem_u32(esm);
    int tid = threadIdx.x;
    int m0 = blockIdx.x * 128;

    const unsigned int* gWhi = blockIdx.y ? g_WhiR : g_WhiL;
    const unsigned int* gWlo = blockIdx.y ? g_WloR : g_WloL;
    const float* bias = blockIdx.y ? br : bl;
    float* C = blockIdx.y ? g_xr : g_xl;

    stage_A_seq(sb, g_hhi, g_hlo, m0, tid);
    stage_W(esm, gWhi, gWlo, tid);
    cp_wait<0>();
    __syncthreads();

    int wid = tid >> 5, lane = tid & 31, g = lane >> 2, q = lane & 3;
    int mb = (wid & 3) * 32;
    int nb = (wid >> 2) * 64;

    float acc[2][8][4];
#pragma unroll
    for (int t = 0; t < 2; t++)
#pragma unroll
        for (int j = 0; j < 8; j++)
#pragma unroll
            for (int c = 0; c < 4; c++) acc[t][j][c] = 0.f;

    pass_mma(acc, sb + 3 * TB, sb, mb, nb, lane);          // (Alo, Whi)
    pass_mma(acc, sb + 2 * TB, sb + 1 * TB, mb, nb, lane); // (Ahi, Wlo)
    pass_mma(acc, sb + 2 * TB, sb, mb, nb, lane);          // (Ahi, Whi)

    float2 biasv[8];
#pragma unroll
    for (int j = 0; j < 8; j++)
        biasv[j] = *(const float2*)&bias[nb + 8 * j + 2 * q];

#pragma unroll
    for (int t = 0; t < 2; t++) {
#pragma unroll
        for (int rr = 0; rr < 2; rr++) {
            int m = m0 + mb + 16 * t + 8 * rr + g;
            if (m < NN) {
#pragma unroll
                for (int j = 0; j < 8; j++) {
                    int cc = nb + 8 * j + 2 * q;
                    *(float2*)&C[(size_t)m * HID + cc] =
                        make_float2(acc[t][j][rr * 2 + 0] + biasv[j].x,
                                    acc[t][j][rr * 2 + 1] + biasv[j].y);
                }
            }
        }
    }
}

// ---------------- layer-0 node projection (K=12) ----------------
__global__ void node_proj12(const float* __restrict__ x,
                            const float* __restrict__ Wl, const float* __restrict__ bl,
                            const float* __restrict__ Wr, const float* __restrict__ br) {
    int idx = blockIdx.x * blockDim.x + threadIdx.x;
    int n = idx >> 7, j = idx & 127;
    float a = __ldg(&bl[j]);
    float b = __ldg(&br[j]);
#pragma unroll
    for (int k = 0; k < 12; k++) {
        float xv = __ldg(&x[n * 12 + k]);
        a = fmaf(xv, __ldg(&Wl[k * HID + j]), a);
        b = fmaf(xv, __ldg(&Wr[k * HID + j]), b);
    }
    g_xl[idx] = a;
    g_xr[idx] = b;
}

// ------- fused per-node: softmax + aggregate + bias + LN + SiLU (+res) ----------
template <bool RES, bool LAST>
__global__ void node_fused_kernel(const float* __restrict__ gat_bias,
                                  const float* __restrict__ lng,
                                  const float* __restrict__ lnb,
                                  float* __restrict__ dout) {
    int n = blockIdx.x * 4 + (threadIdx.x >> 5);
    int lane = threadIdx.x & 31;
    if (n >= NN) return;
    int s0 = g_rowptr[n];
    int s1 = g_rowptr[n + 1];

    float mx = -3.4e38f;
    for (int p = s0 * 4 + lane; p < s1 * 4; p += 32)
        mx = fmaxf(mx, g_score[p]);
    mx = fmaxf(mx, __shfl_xor_sync(0xffffffffu, mx, 4));
    mx = fmaxf(mx, __shfl_xor_sync(0xffffffffu, mx, 8));
    mx = fmaxf(mx, __shfl_xor_sync(0xffffffffu, mx, 16));

    float den = 0.f;
    for (int p = s0 * 4 + lane; p < s1 * 4; p += 32)
        den += __expf(g_score[p] - mx);
    den += __shfl_xor_sync(0xffffffffu, den, 4);
    den += __shfl_xor_sync(0xffffffffu, den, 8);
    den += __shfl_xor_sync(0xffffffffu, den, 16);
    float inv = __fdividef(1.f, den + 1e-16f);

    float acc0 = 0.f, acc1 = 0.f, acc2 = 0.f, acc3 = 0.f;
    for (int i = s0; i < s1; i++) {
        int src = g_sd[i].x;
        float a = 0.f;
        if (lane < 4) a = __expf(g_score[(size_t)i * 4 + lane] - mx) * inv;
        float al0 = __shfl_sync(0xffffffffu, a, 0);
        float al1 = __shfl_sync(0xffffffffu, a, 1);
        float al2 = __shfl_sync(0xffffffffu, a, 2);
        float al3 = __shfl_sync(0xffffffffu, a, 3);
        const float* xl = &g_xl[(size_t)src * HID];
        acc0 = fmaf(xl[0 * DH + lane], al0, acc0);
        acc1 = fmaf(xl[1 * DH + lane], al1, acc1);
        acc2 = fmaf(xl[2 * DH + lane], al2, acc2);
        acc3 = fmaf(xl[3 * DH + lane], al3, acc3);
    }

    float v0 = acc0 + __ldg(&gat_bias[0 * DH + lane]);
    float v1 = acc1 + __ldg(&gat_bias[1 * DH + lane]);
    float v2 = acc2 + __ldg(&gat_bias[2 * DH + lane]);
    float v3 = acc3 + __ldg(&gat_bias[3 * DH + lane]);

    float sm = v0 + v1 + v2 + v3;
#pragma unroll
    for (int off = 16; off; off >>= 1) sm += __shfl_xor_sync(0xffffffffu, sm, off);
    float mean = sm * (1.f / 128.f);
    float d0 = v0 - mean, d1 = v1 - mean, d2 = v2 - mean, d3 = v3 - mean;
    float sq = d0 * d0 + d1 * d1 + d2 * d2 + d3 * d3;
#pragma unroll
    for (int off = 16; off; off >>= 1) sq += __shfl_xor_sync(0xffffffffu, sq, off);
    float rstd = rsqrtf(sq * (1.f / 128.f) + 1e-5f);

#pragma unroll
    for (int h = 0; h < 4; h++) {
        int j = h * DH + lane;
        float d = (h == 0 ? d0 : h == 1 ? d1 : h == 2 ? d2 : d3);
        float t = fmaf(d * rstd, __ldg(&lng[j]), __ldg(&lnb[j]));
        float sil = fast_silu(t);
        float o = RES ? (g_h[n * HID + j] + sil) : sil;
        if (LAST) {
            dout[n * HID + j] = o;
        } else {
            g_h[n * HID + j] = o;
            // bf16 split pair images for the next layer's node GEMM
            float on = __shfl_down_sync(0xffffffffu, o, 1);
            if (!(lane & 1)) {
                float h0, l0, h1, l1;
                bf_split(o, h0, l0);
                bf_split(on, h1, l1);
                g_hhi[(size_t)n * 64 + (j >> 1)] = packbf2(h0, h1);
                g_hlo[(size_t)n * 64 + (j >> 1)] = packbf2(l0, l1);
            }
        }
    }
}

// ---------------- launch ----------------
extern "C" void kernel_launch(void* const* d_in, const int* in_sizes, int n_in,
                              void* d_out, int out_size) {
    const float* x     = (const float*)d_in[0];
    const int*   ei    = (const int*)  d_in[1];
    const float* eattr = (const float*)d_in[2];
    const float* epw   = (const float*)d_in[3];
    const float* epb   = (const float*)d_in[4];
    const float* l0Wl  = (const float*)d_in[5];
    const float* l0bl  = (const float*)d_in[6];
    const float* l0Wr  = (const float*)d_in[7];
    const float* l0br  = (const float*)d_in[8];
    const float* l0We  = (const float*)d_in[9];
    const float* l0att = (const float*)d_in[10];
    const float* l0bias= (const float*)d_in[11];
    const float* Wl    = (const float*)d_in[12];
    const float* bl    = (const float*)d_in[13];
    const float* Wr    = (const float*)d_in[14];
    const float* br    = (const float*)d_in[15];
    const float* We    = (const float*)d_in[16];
    const float* att   = (const float*)d_in[17];
    const float* bias  = (const float*)d_in[18];
    const float* lng   = (const float*)d_in[19];
    const float* lnb   = (const float*)d_in[20];
    float* out = (float*)d_out;

    static bool attr_set = false;
    if (!attr_set) {
        cudaFuncSetAttribute(gemm_edge_score_mma,
                             cudaFuncAttributeMaxDynamicSharedMemorySize, ESM_BYTES);
        cudaFuncSetAttribute(gemm_node_mma,
                             cudaFuncAttributeMaxDynamicSharedMemorySize, ESM_BYTES);
        attr_set = true;
    }

    // CSR build first (eproj needs g_pos)
    zero_kernel<<<(NN + 255) / 256, 256>>>();
    hist_kernel<<<(EE + 255) / 256, 256>>>(ei);
    deg_block_sum<<<NBLK, 1024>>>();
    bsum_scan<<<1, 128>>>();
    rowptr_kernel<<<NBLK, 1024>>>();
    scatter_kernel<<<(EE + 255) / 256, 256>>>(ei);

    // independent prep
    eproj_kernel<<<(EE * 32) / 256, 256>>>(eattr, epw, epb);
    node_proj12<<<(NN * HID) / 256, 256>>>(x, l0Wl, l0bl, l0Wr, l0br);
    wprep_kernel<<<32, 256>>>(l0We, 0);

    // layer 0
    gemm_edge_score_mma<<<EE / 128, 256, ESM_BYTES>>>(l0att);
    node_fused_kernel<false, false><<<NN / 4, 128>>>(l0bias, lng, lnb, nullptr);

    // layers 1..3 (residual)
    for (int i = 0; i < 3; i++) {
        wprep_kernel<<<32, 256>>>(Wl + i * HID * HID, 1);
        wprep_kernel<<<32, 256>>>(Wr + i * HID * HID, 2);
        wprep_kernel<<<32, 256>>>(We + i * HID * HID, 0);
        dim3 ng(NTILES, 2);
        gemm_node_mma<<<ng, 256, ESM_BYTES>>>(bl + i * HID, br + i * HID);
        gemm_edge_score_mma<<<EE / 128, 256, ESM_BYTES>>>(att + i * HID);
        if (i < 2)
            node_fused_kernel<true, false><<<NN / 4, 128>>>(
                bias + i * HID, lng + (i + 1) * HID, lnb + (i + 1) * HID, nullptr);
        else
            node_fused_kernel<true, true><<<NN / 4, 128>>>(
                bias + i * HID, lng + (i + 1) * HID, lnb + (i + 1) * HID, out);
    }
}

// round 14
// speedup vs baseline: 2.6493x; 1.1960x over previous
#include <cuda_runtime.h>
#include <cuda_bf16.h>
#include <math.h>
#include <stdint.h>

#define NN 100000
#define EE 800000
#define HID 128
#define NH 4
#define DH 32
#define NBLK ((NN + 1023) / 1024)   // 98
#define NPAD 100096
#define NTILES ((NN + 127) / 128)   // 782
#define EPAD 68
#define TW (128 * EPAD)             // words per 128-row image (8704)
#define TB (TW * 4)                 // bytes per image (34816)
#define ESM_BYTES (3 * TB)          // Whi | Ahi | Alo(->Wlo) = 104448 B (2 blocks/SM)
#define XLPAD 132                   // xl prefetch row stride (floats)

// ---------------- scratch (static device globals; no allocation) ----------------
__device__ unsigned int g_Ahi[(size_t)EE * 64];   // edge feats bf16-hi pairs (CSR order)
__device__ unsigned int g_Alo[(size_t)EE * 64];
__device__ unsigned int g_hhi[(size_t)NPAD * 64]; // hidden bf16 pair images
__device__ unsigned int g_hlo[(size_t)NPAD * 64];
__device__ float g_xl[NN * HID];
__device__ float g_xr[NN * HID];
__device__ float g_h [NN * HID];
__device__ float g_score[EE * NH];                // CSR-position-indexed
__device__ unsigned int g_WhiE[8192], g_WloE[8192];
__device__ unsigned int g_WhiL[8192], g_WloL[8192];
__device__ unsigned int g_WhiR[8192], g_WloR[8192];
__device__ int g_deg[NN], g_cursor[NN], g_rowptr[NN + 1];
__device__ int g_pos[EE];                         // edge id -> CSR position
__device__ int2 g_sd[EE];                         // (src, dst) per CSR position
__device__ int g_bsum[NBLK], g_boff[NBLK];

// ---------------- helpers ----------------
__device__ __forceinline__ float fast_silu(float z) {
    return __fdividef(z, 1.0f + __expf(-z));
}
__device__ __forceinline__ unsigned int packbf2(float x, float y) {
    __nv_bfloat162 t = __floats2bfloat162_rn(x, y);
    return *(unsigned int*)&t;
}
__device__ __forceinline__ void bf_split(float x, float& hi, float& lo) {
    __nv_bfloat16 h = __float2bfloat16_rn(x);
    hi = __bfloat162float(h);
    lo = x - hi;
}
__device__ __forceinline__ void mma_bf16(float c[4],
                                         unsigned int a0, unsigned int a1,
                                         unsigned int a2, unsigned int a3,
                                         unsigned int b0, unsigned int b1) {
    asm volatile("mma.sync.aligned.m16n8k16.row.col.f32.bf16.bf16.f32 "
                 "{%0,%1,%2,%3}, {%4,%5,%6,%7}, {%8,%9}, {%0,%1,%2,%3};"
                 : "+f"(c[0]), "+f"(c[1]), "+f"(c[2]), "+f"(c[3])
                 : "r"(a0), "r"(a1), "r"(a2), "r"(a3), "r"(b0), "r"(b1));
}
__device__ __forceinline__ void ldsm4(unsigned int r[4], uint32_t addr) {
    asm volatile("ldmatrix.sync.aligned.m8n8.x4.shared.b16 {%0,%1,%2,%3}, [%4];"
                 : "=r"(r[0]), "=r"(r[1]), "=r"(r[2]), "=r"(r[3]) : "r"(addr));
}
__device__ __forceinline__ uint32_t smem_u32(const void* p) {
    uint32_t a;
    asm("{ .reg .u64 t; cvta.to.shared.u64 t, %1; cvt.u32.u64 %0, t; }" : "=r"(a) : "l"(p));
    return a;
}
__device__ __forceinline__ void cp16(uint32_t d, const void* s) {
    size_t gs = __cvta_generic_to_global((void*)s);
    asm volatile("cp.async.cg.shared.global [%0], [%1], 16;"
                 :: "r"(d), "l"((unsigned long long)gs) : "memory");
}
__device__ __forceinline__ void cp_commit() {
    asm volatile("cp.async.commit_group;" ::: "memory");
}
template <int N>
__device__ __forceinline__ void cp_wait() {
    asm volatile("cp.async.wait_group %0;" :: "n"(N) : "memory");
}

// ---------------- CSR build (by dst) ----------------
__global__ void zero_kernel() {
    int i = blockIdx.x * blockDim.x + threadIdx.x;
    if (i < NN) { g_deg[i] = 0; g_cursor[i] = 0; }
    if (i < (NPAD - NN) * 64) {   // zero pad rows of h images
        g_hhi[(size_t)NN * 64 + i] = 0;
        g_hlo[(size_t)NN * 64 + i] = 0;
    }
}
__global__ void hist_kernel(const int* __restrict__ ei) {
    int e = blockIdx.x * blockDim.x + threadIdx.x;
    if (e < EE) atomicAdd(&g_deg[ei[EE + e]], 1);
}
__global__ void deg_block_sum() {
    __shared__ int sh[1024];
    int i = blockIdx.x * 1024 + threadIdx.x;
    sh[threadIdx.x] = (i < NN) ? g_deg[i] : 0;
    __syncthreads();
    for (int off = 512; off; off >>= 1) {
        if (threadIdx.x < off) sh[threadIdx.x] += sh[threadIdx.x + off];
        __syncthreads();
    }
    if (threadIdx.x == 0) g_bsum[blockIdx.x] = sh[0];
}
__global__ void bsum_scan() {
    __shared__ int sh[128];
    int t = threadIdx.x;
    int v = (t < NBLK) ? g_bsum[t] : 0;
    sh[t] = v;
    __syncthreads();
    for (int off = 1; off < 128; off <<= 1) {
        int u = (t >= off) ? sh[t - off] : 0;
        __syncthreads();
        sh[t] += u;
        __syncthreads();
    }
    if (t < NBLK) g_boff[t] = sh[t] - v;
}
__global__ void rowptr_kernel() {
    __shared__ int sh[1024];
    int i = blockIdx.x * 1024 + threadIdx.x;
    int v = (i < NN) ? g_deg[i] : 0;
    sh[threadIdx.x] = v;
    __syncthreads();
    for (int off = 1; off < 1024; off <<= 1) {
        int u = (threadIdx.x >= off) ? sh[threadIdx.x - off] : 0;
        __syncthreads();
        sh[threadIdx.x] += u;
        __syncthreads();
    }
    if (i < NN) g_rowptr[i + 1] = sh[threadIdx.x] + g_boff[blockIdx.x];
    if (i == 0) g_rowptr[0] = 0;
}
__global__ void scatter_kernel(const int* __restrict__ ei) {
    int e = blockIdx.x * blockDim.x + threadIdx.x;
    if (e < EE) {
        int src = ei[e];
        int d = ei[EE + e];
        int pos = g_rowptr[d] + atomicAdd(&g_cursor[d], 1);
        g_pos[e] = pos;
        g_sd[pos] = make_int2(src, d);
    }
}

// -------- edge feature projection: bf16 hi/lo images at CSR positions ----------
__global__ void eproj_kernel(const float* __restrict__ attr,
                             const float* __restrict__ W,
                             const float* __restrict__ b) {
    int idx = blockIdx.x * blockDim.x + threadIdx.x;   // E*32 threads
    int e = idx >> 5, c4 = (idx & 31) << 2;
    float a0 = __ldg(&attr[e * 3 + 0]);
    float a1 = __ldg(&attr[e * 3 + 1]);
    float a2 = __ldg(&attr[e * 3 + 2]);
    float v[4];
#pragma unroll
    for (int u = 0; u < 4; u++) {
        int j = c4 + u;
        float z = __ldg(&b[j]);
        z = fmaf(a0, __ldg(&W[j]),           z);
        z = fmaf(a1, __ldg(&W[HID + j]),     z);
        z = fmaf(a2, __ldg(&W[2 * HID + j]), z);
        v[u] = fast_silu(z);
    }
    float h0, l0, h1, l1, h2, l2, h3, l3;
    bf_split(v[0], h0, l0); bf_split(v[1], h1, l1);
    bf_split(v[2], h2, l2); bf_split(v[3], h3, l3);
    int pos = __ldg(&g_pos[e]);
    size_t base = (size_t)pos * 64 + (c4 >> 1);
    *(uint2*)&g_Ahi[base] = make_uint2(packbf2(h0, h1), packbf2(h2, h3));
    *(uint2*)&g_Alo[base] = make_uint2(packbf2(l0, l1), packbf2(l2, l3));
}

// ---------------- W image prep: 0 -> We, 1 -> Wl, 2 -> Wr ----------------
__global__ void wprep_kernel(const float* __restrict__ W, int which) {
    int idx = blockIdx.x * 256 + threadIdx.x;   // 8192
    int n = idx >> 6, kw = idx & 63;
    float w0 = __ldg(&W[(2 * kw) * HID + n]);
    float w1 = __ldg(&W[(2 * kw + 1) * HID + n]);
    float h0, l0, h1, l1;
    bf_split(w0, h0, l0);
    bf_split(w1, h1, l1);
    unsigned int* hi = (which == 0) ? g_WhiE : (which == 1) ? g_WhiL : g_WhiR;
    unsigned int* lo = (which == 0) ? g_WloE : (which == 1) ? g_WloL : g_WloR;
    hi[idx] = packbf2(h0, h1);
    lo[idx] = packbf2(l0, l1);
}

// ---- one bf16 mma pass over the tile via ldmatrix (8 K-steps) ----
__device__ __forceinline__ void pass_mma(float acc[2][8][4],
                                         uint32_t aBase, uint32_t bBase,
                                         int mb, int nb, int lane) {
    uint32_t aoff = (uint32_t)(((mb + (lane & 15)) * EPAD + ((lane >> 4) << 2)) * 4);
    uint32_t boff = (uint32_t)(((nb + (lane & 7) + ((lane >> 4) << 3)) * EPAD
                                + (((lane >> 3) & 1) << 2)) * 4);
    uint32_t a0a = aBase + aoff;
    uint32_t a1a = a0a + 16 * EPAD * 4;
    uint32_t bja = bBase + boff;
#pragma unroll
    for (int ks = 0; ks < 8; ks++) {
        unsigned int a0[4], a1[4];
        ldsm4(a0, a0a + ks * 32);
        ldsm4(a1, a1a + ks * 32);
        unsigned int b[4][4];
#pragma unroll
        for (int jj = 0; jj < 4; jj++)
            ldsm4(b[jj], bja + (uint32_t)(jj * 16 * EPAD * 4) + ks * 32);
#pragma unroll
        for (int jj = 0; jj < 4; jj++) {
            mma_bf16(acc[0][2 * jj + 0], a0[0], a0[1], a0[2], a0[3], b[jj][0], b[jj][1]);
            mma_bf16(acc[0][2 * jj + 1], a0[0], a0[1], a0[2], a0[3], b[jj][2], b[jj][3]);
            mma_bf16(acc[1][2 * jj + 0], a1[0], a1[1], a1[2], a1[3], b[jj][0], b[jj][1]);
            mma_bf16(acc[1][2 * jj + 1], a1[0], a1[1], a1[2], a1[3], b[jj][2], b[jj][3]);
        }
    }
}

// ---- staging helpers ----
// images: Whi @ sb, Ahi @ sb+TB, Alo @ sb+2TB (Alo later reused for Wlo)
__device__ __forceinline__ void stage_all(uint32_t sb, const unsigned int* ghi,
                                          const unsigned int* glo,
                                          const unsigned int* gWhi,
                                          int m0, int tid) {
#pragma unroll
    for (int i = 0; i < 8; i++) {
        int idx = i * 256 + tid;
        int row = idx >> 4, c = (idx & 15) << 2;
        uint32_t doff = (uint32_t)(row * EPAD + c) * 4;
        cp16(sb + TB + doff, &ghi[(size_t)(m0 + row) * 64 + c]);
        cp16(sb + 2 * TB + doff, &glo[(size_t)(m0 + row) * 64 + c]);
        cp16(sb + doff, &gWhi[(size_t)row * 64 + c]);
    }
    cp_commit();
}
__device__ __forceinline__ void stage_Wlo(uint32_t dst, const unsigned int* gWlo,
                                          int tid) {
#pragma unroll
    for (int i = 0; i < 8; i++) {
        int idx = i * 256 + tid;
        int row = idx >> 4, c = (idx & 15) << 2;
        cp16(dst + (uint32_t)(row * EPAD + c) * 4, &gWlo[(size_t)row * 64 + c]);
    }
    cp_commit();
}
// ---- prefetch 64 xl rows (CSR positions p0..p0+63) into a dead smem image ----
__device__ __forceinline__ void prefetch_xl(uint32_t dstbase, int p0, int tid) {
#pragma unroll
    for (int i = 0; i < 8; i++) {
        int idx = i * 256 + tid;
        int row = idx >> 5;
        int c = (idx & 31) << 2;
        int src = __ldg(&g_sd[p0 + row].x);
        cp16(dstbase + (uint32_t)(row * XLPAD + c) * 4,
             &g_xl[(size_t)src * HID + c]);
    }
    cp_commit();
}

// ========= edge GEMM + fused score (3-image smem, 2 blocks/SM) =========
__global__ __launch_bounds__(256, 2) void gemm_edge_score_mma(
        const float* __restrict__ att) {
    extern __shared__ __align__(16) unsigned int esm[];
    uint32_t sb = smem_u32(esm);
    int tid = threadIdx.x;
    int m0 = blockIdx.x * 128;

    stage_all(sb, g_Ahi, g_Alo, g_WhiE, m0, tid);
    cp_wait<0>();
    __syncthreads();

    int wid = tid >> 5, lane = tid & 31, g = lane >> 2, q = lane & 3;
    int mb = (wid & 3) * 32;
    int nb = (wid >> 2) * 64;

    float acc[2][8][4];
#pragma unroll
    for (int t = 0; t < 2; t++)
#pragma unroll
        for (int j = 0; j < 8; j++)
#pragma unroll
            for (int c = 0; c < 4; c++) acc[t][j][c] = 0.f;

    // p0: (Alo, Whi) — Alo dead afterwards
    pass_mma(acc, sb + 2 * TB, sb, mb, nb, lane);
    __syncthreads();
    stage_Wlo(sb + 2 * TB, g_WloE, tid);            // Wlo -> Alo space (group W)

    // p1: (Ahi, Whi) — Whi dead afterwards (Wlo load overlaps)
    pass_mma(acc, sb + TB, sb, mb, nb, lane);
    __syncthreads();
    prefetch_xl(sb, m0, tid);                        // xl rows 0..63 -> Whi space (group X)
    cp_wait<1>();                                    // W done (X may fly)
    __syncthreads();

    // p2: (Ahi, Wlo) (xl load overlaps)
    pass_mma(acc, sb + TB, sb + 2 * TB, mb, nb, lane);
    cp_wait<0>();
    __syncthreads();

    // fused epilogue: rows 0..63 xl from smem; rows 64..127 xl via L2; xr via L1
    const float* xlb0 = (const float*)esm;
    float2 attv[8];
#pragma unroll
    for (int j = 0; j < 8; j++)
        attv[j] = *(const float2*)&att[nb + 8 * j + 2 * q];

#pragma unroll
    for (int t = 0; t < 2; t++) {
#pragma unroll
        for (int rr = 0; rr < 2; rr++) {
            int row = mb + 16 * t + 8 * rr + g;
            int pos = m0 + row;
            int2 sd = __ldg(&g_sd[pos]);
            const float* xlp = (row < 64) ? (xlb0 + row * XLPAD)
                                          : &g_xl[(size_t)sd.x * HID];
            const float* xrp = &g_xr[(size_t)sd.y * HID];
            float p0 = 0.f, p1 = 0.f;
#pragma unroll
            for (int j = 0; j < 8; j++) {
                int cc = nb + 8 * j + 2 * q;
                float2 xl = *(const float2*)&xlp[cc];
                float2 xr = *(const float2*)&xrp[cc];
                float e0 = acc[t][j][rr * 2 + 0] + xl.x + xr.x;
                float e1 = acc[t][j][rr * 2 + 1] + xl.y + xr.y;
                e0 = (e0 > 0.f) ? e0 : 0.2f * e0;
                e1 = (e1 > 0.f) ? e1 : 0.2f * e1;
                float ps = fmaf(e0, attv[j].x, e1 * attv[j].y);
                if (j < 4) p0 += ps; else p1 += ps;
            }
            p0 += __shfl_xor_sync(0xffffffffu, p0, 1);
            p0 += __shfl_xor_sync(0xffffffffu, p0, 2);
            p1 += __shfl_xor_sync(0xffffffffu, p1, 1);
            p1 += __shfl_xor_sync(0xffffffffu, p1, 2);
            if (q == 0)
                *(float2*)&g_score[(size_t)pos * 4 + (nb >> 5)] =
                    make_float2(p0, p1);
        }
    }
}

// ============ node GEMM (3-image smem, 2 blocks/SM) ==========
__global__ __launch_bounds__(256, 2) void gemm_node_mma(
        const float* __restrict__ bl, const float* __restrict__ br) {
    extern __shared__ __align__(16) unsigned int esm[];
    uint32_t sb = smem_u32(esm);
    int tid = threadIdx.x;
    int m0 = blockIdx.x * 128;

    const unsigned int* gWhi = blockIdx.y ? g_WhiR : g_WhiL;
    const unsigned int* gWlo = blockIdx.y ? g_WloR : g_WloL;
    const float* bias = blockIdx.y ? br : bl;
    float* C = blockIdx.y ? g_xr : g_xl;

    stage_all(sb, g_hhi, g_hlo, gWhi, m0, tid);
    cp_wait<0>();
    __syncthreads();

    int wid = tid >> 5, lane = tid & 31, g = lane >> 2, q = lane & 3;
    int mb = (wid & 3) * 32;
    int nb = (wid >> 2) * 64;

    float acc[2][8][4];
#pragma unroll
    for (int t = 0; t < 2; t++)
#pragma unroll
        for (int j = 0; j < 8; j++)
#pragma unroll
            for (int c = 0; c < 4; c++) acc[t][j][c] = 0.f;

    pass_mma(acc, sb + 2 * TB, sb, mb, nb, lane);   // (Alo, Whi)
    __syncthreads();
    stage_Wlo(sb + 2 * TB, gWlo, tid);              // Wlo -> Alo space
    pass_mma(acc, sb + TB, sb, mb, nb, lane);       // (Ahi, Whi), overlaps Wlo load
    cp_wait<0>();
    __syncthreads();
    pass_mma(acc, sb + TB, sb + 2 * TB, mb, nb, lane); // (Ahi, Wlo)

    float2 biasv[8];
#pragma unroll
    for (int j = 0; j < 8; j++)
        biasv[j] = *(const float2*)&bias[nb + 8 * j + 2 * q];

#pragma unroll
    for (int t = 0; t < 2; t++) {
#pragma unroll
        for (int rr = 0; rr < 2; rr++) {
            int m = m0 + mb + 16 * t + 8 * rr + g;
            if (m < NN) {
#pragma unroll
                for (int j = 0; j < 8; j++) {
                    int cc = nb + 8 * j + 2 * q;
                    *(float2*)&C[(size_t)m * HID + cc] =
                        make_float2(acc[t][j][rr * 2 + 0] + biasv[j].x,
                                    acc[t][j][rr * 2 + 1] + biasv[j].y);
                }
            }
        }
    }
}

// ---------------- layer-0 node projection (K=12) ----------------
__global__ void node_proj12(const float* __restrict__ x,
                            const float* __restrict__ Wl, const float* __restrict__ bl,
                            const float* __restrict__ Wr, const float* __restrict__ br) {
    int idx = blockIdx.x * blockDim.x + threadIdx.x;
    int n = idx >> 7, j = idx & 127;
    float a = __ldg(&bl[j]);
    float b = __ldg(&br[j]);
#pragma unroll
    for (int k = 0; k < 12; k++) {
        float xv = __ldg(&x[n * 12 + k]);
        a = fmaf(xv, __ldg(&Wl[k * HID + j]), a);
        b = fmaf(xv, __ldg(&Wr[k * HID + j]), b);
    }
    g_xl[idx] = a;
    g_xr[idx] = b;
}

// ------- fused per-node: softmax + aggregate + bias + LN + SiLU (+res) ----------
template <bool RES, bool LAST>
__global__ void node_fused_kernel(const float* __restrict__ gat_bias,
                                  const float* __restrict__ lng,
                                  const float* __restrict__ lnb,
                                  float* __restrict__ dout) {
    int n = blockIdx.x * 4 + (threadIdx.x >> 5);
    int lane = threadIdx.x & 31;
    if (n >= NN) return;
    int s0 = g_rowptr[n];
    int s1 = g_rowptr[n + 1];

    float mx = -3.4e38f;
    for (int p = s0 * 4 + lane; p < s1 * 4; p += 32)
        mx = fmaxf(mx, g_score[p]);
    mx = fmaxf(mx, __shfl_xor_sync(0xffffffffu, mx, 4));
    mx = fmaxf(mx, __shfl_xor_sync(0xffffffffu, mx, 8));
    mx = fmaxf(mx, __shfl_xor_sync(0xffffffffu, mx, 16));

    float den = 0.f;
    for (int p = s0 * 4 + lane; p < s1 * 4; p += 32)
        den += __expf(g_score[p] - mx);
    den += __shfl_xor_sync(0xffffffffu, den, 4);
    den += __shfl_xor_sync(0xffffffffu, den, 8);
    den += __shfl_xor_sync(0xffffffffu, den, 16);
    float inv = __fdividef(1.f, den + 1e-16f);

    float acc0 = 0.f, acc1 = 0.f, acc2 = 0.f, acc3 = 0.f;
    for (int i = s0; i < s1; i++) {
        int src = g_sd[i].x;
        float a = 0.f;
        if (lane < 4) a = __expf(g_score[(size_t)i * 4 + lane] - mx) * inv;
        float al0 = __shfl_sync(0xffffffffu, a, 0);
        float al1 = __shfl_sync(0xffffffffu, a, 1);
        float al2 = __shfl_sync(0xffffffffu, a, 2);
        float al3 = __shfl_sync(0xffffffffu, a, 3);
        const float* xl = &g_xl[(size_t)src * HID];
        acc0 = fmaf(xl[0 * DH + lane], al0, acc0);
        acc1 = fmaf(xl[1 * DH + lane], al1, acc1);
        acc2 = fmaf(xl[2 * DH + lane], al2, acc2);
        acc3 = fmaf(xl[3 * DH + lane], al3, acc3);
    }

    float v0 = acc0 + __ldg(&gat_bias[0 * DH + lane]);
    float v1 = acc1 + __ldg(&gat_bias[1 * DH + lane]);
    float v2 = acc2 + __ldg(&gat_bias[2 * DH + lane]);
    float v3 = acc3 + __ldg(&gat_bias[3 * DH + lane]);

    float sm = v0 + v1 + v2 + v3;
#pragma unroll
    for (int off = 16; off; off >>= 1) sm += __shfl_xor_sync(0xffffffffu, sm, off);
    float mean = sm * (1.f / 128.f);
    float d0 = v0 - mean, d1 = v1 - mean, d2 = v2 - mean, d3 = v3 - mean;
    float sq = d0 * d0 + d1 * d1 + d2 * d2 + d3 * d3;
#pragma unroll
    for (int off = 16; off; off >>= 1) sq += __shfl_xor_sync(0xffffffffu, sq, off);
    float rstd = rsqrtf(sq * (1.f / 128.f) + 1e-5f);

#pragma unroll
    for (int h = 0; h < 4; h++) {
        int j = h * DH + lane;
        float d = (h == 0 ? d0 : h == 1 ? d1 : h == 2 ? d2 : d3);
        float t = fmaf(d * rstd, __ldg(&lng[j]), __ldg(&lnb[j]));
        float sil = fast_silu(t);
        float o = RES ? (g_h[n * HID + j] + sil) : sil;
        if (LAST) {
            dout[n * HID + j] = o;
        } else {
            g_h[n * HID + j] = o;
            float on = __shfl_down_sync(0xffffffffu, o, 1);
            if (!(lane & 1)) {
                float h0, l0, h1, l1;
                bf_split(o, h0, l0);
                bf_split(on, h1, l1);
                g_hhi[(size_t)n * 64 + (j >> 1)] = packbf2(h0, h1);
                g_hlo[(size_t)n * 64 + (j >> 1)] = packbf2(l0, l1);
            }
        }
    }
}

// ---------------- launch ----------------
extern "C" void kernel_launch(void* const* d_in, const int* in_sizes, int n_in,
                              void* d_out, int out_size) {
    const float* x     = (const float*)d_in[0];
    const int*   ei    = (const int*)  d_in[1];
    const float* eattr = (const float*)d_in[2];
    const float* epw   = (const float*)d_in[3];
    const float* epb   = (const float*)d_in[4];
    const float* l0Wl  = (const float*)d_in[5];
    const float* l0bl  = (const float*)d_in[6];
    const float* l0Wr  = (const float*)d_in[7];
    const float* l0br  = (const float*)d_in[8];
    const float* l0We  = (const float*)d_in[9];
    const float* l0att = (const float*)d_in[10];
    const float* l0bias= (const float*)d_in[11];
    const float* Wl    = (const float*)d_in[12];
    const float* bl    = (const float*)d_in[13];
    const float* Wr    = (const float*)d_in[14];
    const float* br    = (const float*)d_in[15];
    const float* We    = (const float*)d_in[16];
    const float* att   = (const float*)d_in[17];
    const float* bias  = (const float*)d_in[18];
    const float* lng   = (const float*)d_in[19];
    const float* lnb   = (const float*)d_in[20];
    float* out = (float*)d_out;

    static bool attr_set = false;
    if (!attr_set) {
        cudaFuncSetAttribute(gemm_edge_score_mma,
                             cudaFuncAttributeMaxDynamicSharedMemorySize, ESM_BYTES);
        cudaFuncSetAttribute(gemm_node_mma,
                             cudaFuncAttributeMaxDynamicSharedMemorySize, ESM_BYTES);
        attr_set = true;
    }

    // CSR build first (eproj needs g_pos)
    zero_kernel<<<(NN + 255) / 256, 256>>>();
    hist_kernel<<<(EE + 255) / 256, 256>>>(ei);
    deg_block_sum<<<NBLK, 1024>>>();
    bsum_scan<<<1, 128>>>();
    rowptr_kernel<<<NBLK, 1024>>>();
    scatter_kernel<<<(EE + 255) / 256, 256>>>(ei);

    // independent prep
    eproj_kernel<<<(EE * 32) / 256, 256>>>(eattr, epw, epb);
    node_proj12<<<(NN * HID) / 256, 256>>>(x, l0Wl, l0bl, l0Wr, l0br);
    wprep_kernel<<<32, 256>>>(l0We, 0);

    // layer 0
    gemm_edge_score_mma<<<EE / 128, 256, ESM_BYTES>>>(l0att);
    node_fused_kernel<false, false><<<NN / 4, 128>>>(l0bias, lng, lnb, nullptr);

    // layers 1..3 (residual)
    for (int i = 0; i < 3; i++) {
        wprep_kernel<<<32, 256>>>(Wl + i * HID * HID, 1);
        wprep_kernel<<<32, 256>>>(Wr + i * HID * HID, 2);
        wprep_kernel<<<32, 256>>>(We + i * HID * HID, 0);
        dim3 ng(NTILES, 2);
        gemm_node_mma<<<ng, 256, ESM_BYTES>>>(bl + i * HID, br + i * HID);
        gemm_edge_score_mma<<<EE / 128, 256, ESM_BYTES>>>(att + i * HID);
        if (i < 2)
            node_fused_kernel<true, false><<<NN / 4, 128>>>(
                bias + i * HID, lng + (i + 1) * HID, lnb + (i + 1) * HID, nullptr);
        else
            node_fused_kernel<true, true><<<NN / 4, 128>>>(
                bias + i * HID, lng + (i + 1) * HID, lnb + (i + 1) * HID, out);
    }
}